// round 5
// baseline (speedup 1.0000x reference)
#include <cuda_runtime.h>
#include <cstdint>

// Problem constants (fixed by the reference)
#define NN   50000
#define EE   400000
#define NH   4
#define CD   128
#define HC   512     // NH * CD
#define NG   64

// ---------------- device scratch (no allocation allowed) ----------------
__device__ float g_xl[(size_t)NN * HC];      // 102.4 MB
__device__ float g_xr[(size_t)NN * HC];      // 102.4 MB
__device__ float g_agg[(size_t)NN * HC];     // 102.4 MB
__device__ float g_h[(size_t)NN * CD];       // 25.6 MB
__device__ float g_e[(size_t)EE * NH];       // 6.4 MB (scores, then exp'd scores)
__device__ int   g_nmax[NN * NH];            // encoded-float segment max
__device__ float g_denom[NN * NH];
__device__ float g_gsum[NG * CD];
__device__ float g_gcnt[NG];
__device__ int   g_is64;

// ---------------- helpers ----------------
__device__ __forceinline__ long long ld_idx(const void* p, long long i, int is64) {
    if (is64) return ((const long long*)p)[i];
    return (long long)((const int*)p)[i];
}
// monotone float <-> int encoding for atomicMax over signed floats
__device__ __forceinline__ int enc_f(float f) {
    int i = __float_as_int(f);
    return (i >= 0) ? i : (i ^ 0x7FFFFFFF);
}
__device__ __forceinline__ float dec_f(int i) {
    return __int_as_float((i >= 0) ? i : (i ^ 0x7FFFFFFF));
}
#define ENC_NEG_INF 0x807FFFFF   // enc_f(-inf)

// ---------------- dtype detection (int32 vs int64 index buffers) ----------------
__global__ void k_detect(const unsigned int* __restrict__ w, int npairs) {
    __shared__ int s_any;
    if (threadIdx.x == 0) s_any = 0;
    __syncthreads();
    int any = 0;
    for (int i = threadIdx.x; i < npairs; i += blockDim.x)
        if (w[2 * i + 1] != 0u) any = 1;
    if (any) atomicOr(&s_any, 1);
    __syncthreads();
    if (threadIdx.x == 0) g_is64 = s_any ? 0 : 1;
}

// ---------------- fills ----------------
__global__ void k_fill_f(float* __restrict__ p, float v, int n) {
    int i = blockIdx.x * blockDim.x + threadIdx.x;
    if (i < n) p[i] = v;
}
__global__ void k_fill_i(int* __restrict__ p, int v, int n) {
    int i = blockIdx.x * blockDim.x + threadIdx.x;
    if (i < n) p[i] = v;
}

// ---------------- SGEMM: C[M,N] = A[M,K] @ B[K,N] + bias[N] ----------------
// 128x128 block tile, 8x8 per-thread microtile, BK=8, 256 threads.
__global__ __launch_bounds__(256) void k_sgemm(
    const float* __restrict__ A, const float* __restrict__ B,
    const float* __restrict__ bias, float* __restrict__ Cout,
    int M, int N, int K)
{
    __shared__ float As[8][128];
    __shared__ float Bs[8][128];
    const int bm = blockIdx.y * 128, bn = blockIdx.x * 128;
    const int tid = threadIdx.x;
    const int tr = tid >> 4, tc = tid & 15;

    float acc[8][8];
#pragma unroll
    for (int i = 0; i < 8; i++)
#pragma unroll
        for (int j = 0; j < 8; j++) acc[i][j] = 0.f;

    for (int k0 = 0; k0 < K; k0 += 8) {
#pragma unroll
        for (int t = 0; t < 4; t++) {          // A tile: 128x8
            int i = tid + t * 256;
            int r = i >> 3, c = i & 7;
            int gm = bm + r, gk = k0 + c;
            As[c][r] = (gm < M && gk < K) ? A[(size_t)gm * K + gk] : 0.f;
        }
#pragma unroll
        for (int t = 0; t < 4; t++) {          // B tile: 8x128
            int i = tid + t * 256;
            int r = i >> 7, c = i & 127;
            int gk = k0 + r, gn = bn + c;
            Bs[r][c] = (gk < K && gn < N) ? B[(size_t)gk * N + gn] : 0.f;
        }
        __syncthreads();
#pragma unroll
        for (int kk = 0; kk < 8; kk++) {
            float a[8], b[8];
#pragma unroll
            for (int i = 0; i < 8; i++) a[i] = As[kk][tr * 8 + i];
#pragma unroll
            for (int j = 0; j < 8; j++) b[j] = Bs[kk][tc * 8 + j];
#pragma unroll
            for (int i = 0; i < 8; i++)
#pragma unroll
                for (int j = 0; j < 8; j++) acc[i][j] += a[i] * b[j];
        }
        __syncthreads();
    }
#pragma unroll
    for (int i = 0; i < 8; i++) {
        int gm = bm + tr * 8 + i;
        if (gm >= M) continue;
#pragma unroll
        for (int j = 0; j < 8; j++) {
            int gn = bn + tc * 8 + j;
            if (gn < N) Cout[(size_t)gm * N + gn] = acc[i][j] + bias[gn];
        }
    }
}

// ---------------- edge pass 1: scores + segment max ----------------
// one warp per edge; per head: 128-dim leaky_relu(xl[s]+xr[d]) . att[h]
__global__ void k_scores(const void* __restrict__ eidx,
                         const float* __restrict__ xl, const float* __restrict__ xr,
                         const float* __restrict__ att,
                         float* __restrict__ eout, int* __restrict__ nmax, int E)
{
    int gw = (blockIdx.x * blockDim.x + threadIdx.x) >> 5;
    int lane = threadIdx.x & 31;
    if (gw >= E) return;
    int is64 = g_is64;
    long long s = ld_idx(eidx, gw, is64);
    long long d = ld_idx(eidx, (long long)E + gw, is64);
    const float4* xls = (const float4*)(xl + (size_t)s * HC);
    const float4* xrd = (const float4*)(xr + (size_t)d * HC);
    const float4* at4 = (const float4*)att;
#pragma unroll
    for (int h = 0; h < NH; h++) {
        float4 a = xls[h * 32 + lane];
        float4 b = xrd[h * 32 + lane];
        float4 w = at4[h * 32 + lane];
        float m0 = a.x + b.x; m0 = m0 > 0.f ? m0 : 0.2f * m0;
        float m1 = a.y + b.y; m1 = m1 > 0.f ? m1 : 0.2f * m1;
        float m2 = a.z + b.z; m2 = m2 > 0.f ? m2 : 0.2f * m2;
        float m3 = a.w + b.w; m3 = m3 > 0.f ? m3 : 0.2f * m3;
        float sum = m0 * w.x + m1 * w.y + m2 * w.z + m3 * w.w;
#pragma unroll
        for (int o = 16; o > 0; o >>= 1) sum += __shfl_xor_sync(0xffffffffu, sum, o);
        if (lane == 0) {
            eout[(size_t)gw * NH + h] = sum;
            atomicMax(&nmax[(int)d * NH + h], enc_f(sum));
        }
    }
}

// ---------------- edge pass 2: exp + segment sum ----------------
__global__ void k_exp(const void* __restrict__ eidx, float* __restrict__ ebuf,
                      const int* __restrict__ nmax, float* __restrict__ denom, int E)
{
    int t = blockIdx.x * blockDim.x + threadIdx.x;
    if (t >= E * NH) return;
    int edge = t >> 2, h = t & 3;
    int is64 = g_is64;
    long long d = ld_idx(eidx, (long long)E + edge, is64);
    float mx = dec_f(nmax[(int)d * NH + h]);
    float ee = __expf(ebuf[t] - mx);
    ebuf[t] = ee;
    atomicAdd(&denom[(int)d * NH + h], ee);
}

// ---------------- edge pass 3: weighted aggregation ----------------
__global__ void k_agg(const void* __restrict__ eidx, const float* __restrict__ ebuf,
                      const float* __restrict__ denom, const float* __restrict__ xl,
                      float* __restrict__ agg, int E)
{
    int gw = (blockIdx.x * blockDim.x + threadIdx.x) >> 5;
    int lane = threadIdx.x & 31;
    if (gw >= E) return;
    int is64 = g_is64;
    long long s = ld_idx(eidx, gw, is64);
    long long d = ld_idx(eidx, (long long)E + gw, is64);
    const float4* xls = (const float4*)(xl + (size_t)s * HC);
#pragma unroll
    for (int h = 0; h < NH; h++) {
        float alpha = ebuf[(size_t)gw * NH + h] / denom[(int)d * NH + h];
        float4 a = xls[h * 32 + lane];
        float* dst = agg + (size_t)d * HC + h * CD + lane * 4;
        atomicAdd(dst + 0, alpha * a.x);
        atomicAdd(dst + 1, alpha * a.y);
        atomicAdd(dst + 2, alpha * a.z);
        atomicAdd(dst + 3, alpha * a.w);
    }
}

// ---------------- epilogue: head mean + bias + elu ----------------
__global__ void k_epi(const float* __restrict__ agg, const float* __restrict__ bias,
                      float* __restrict__ hout, int N)
{
    int t = blockIdx.x * blockDim.x + threadIdx.x;
    if (t >= N * CD) return;
    int n = t >> 7, c = t & 127;
    const float* p = agg + (size_t)n * HC + c;
    float v = 0.25f * (p[0] + p[128] + p[256] + p[384]) + bias[c];
    hout[t] = v > 0.f ? v : (expf(v) - 1.f);
}

// ---------------- global mean pool (batch is sorted) ----------------
__global__ void k_pool(const float* __restrict__ h, const void* __restrict__ batch, int N)
{
    int c = threadIdx.x;                 // 128 threads = feature dim
    int n0 = blockIdx.x * 64;
    int n1 = n0 + 64; if (n1 > N) n1 = N;
    int is64 = g_is64;
    long long cur = -1; float acc = 0.f, cnt = 0.f;
    for (int n = n0; n < n1; n++) {
        long long g = ld_idx(batch, n, is64);
        if (g != cur) {
            if (cur >= 0) {
                atomicAdd(&g_gsum[(int)cur * CD + c], acc);
                if (c == 0) atomicAdd(&g_gcnt[(int)cur], cnt);
            }
            cur = g; acc = 0.f; cnt = 0.f;
        }
        acc += h[(size_t)n * CD + c];
        cnt += 1.f;
    }
    if (cur >= 0) {
        atomicAdd(&g_gsum[(int)cur * CD + c], acc);
        if (c == 0) atomicAdd(&g_gcnt[(int)cur], cnt);
    }
}

// ---------------- final linear: out = (gsum/cnt) @ W + b ----------------
__global__ void k_final(const float* __restrict__ W, const float* __restrict__ b,
                        float* __restrict__ out)
{
    int t = blockIdx.x * blockDim.x + threadIdx.x;
    if (t >= NG * CD) return;
    int g = t >> 7, z = t & 127;
    float inv = 1.f / fmaxf(g_gcnt[g], 1.f);
    float acc = 0.f;
#pragma unroll 8
    for (int c = 0; c < CD; c++)
        acc += g_gsum[g * CD + c] * W[c * CD + z];
    out[t] = acc * inv + b[z];
}

// ---------------- host orchestration ----------------
extern "C" void kernel_launch(void* const* d_in, const int* in_sizes, int n_in,
                              void* d_out, int out_size)
{
    const float* x     = (const float*)d_in[0];
    const void*  eidx  = d_in[1];
    const void*  batch = d_in[2];
    const float* lin_W = (const float*)d_in[21];
    const float* lin_b = (const float*)d_in[22];

    const int N = in_sizes[2];          // 50000
    const int E = in_sizes[1] / 2;      // 400000

    float *xl, *xr, *agg, *hbuf, *ebuf, *denom, *gsum, *gcnt; int* nmax;
    cudaGetSymbolAddress((void**)&xl,    g_xl);
    cudaGetSymbolAddress((void**)&xr,    g_xr);
    cudaGetSymbolAddress((void**)&agg,   g_agg);
    cudaGetSymbolAddress((void**)&hbuf,  g_h);
    cudaGetSymbolAddress((void**)&ebuf,  g_e);
    cudaGetSymbolAddress((void**)&nmax,  g_nmax);
    cudaGetSymbolAddress((void**)&denom, g_denom);
    cudaGetSymbolAddress((void**)&gsum,  g_gsum);
    cudaGetSymbolAddress((void**)&gcnt,  g_gcnt);

    // 0. detect index dtype (int32 vs int64)
    k_detect<<<1, 256>>>((const unsigned int*)eidx, 4096);

    const float* hin = x;
    int Kin = 3;
    for (int l = 0; l < 3; l++) {
        const float* Wl  = (const float*)d_in[3 + 6 * l + 0];
        const float* bl  = (const float*)d_in[3 + 6 * l + 1];
        const float* Wr  = (const float*)d_in[3 + 6 * l + 2];
        const float* br  = (const float*)d_in[3 + 6 * l + 3];
        const float* att = (const float*)d_in[3 + 6 * l + 4];
        const float* bb  = (const float*)d_in[3 + 6 * l + 5];

        // GEMMs: xl = h @ Wl + bl ; xr = h @ Wr + br   (N x 512, K = Kin)
        dim3 gg((HC + 127) / 128, (N + 127) / 128);
        k_sgemm<<<gg, 256>>>(hin, Wl, bl, xl, N, HC, Kin);
        k_sgemm<<<gg, 256>>>(hin, Wr, br, xr, N, HC, Kin);

        // init per-layer accumulators
        k_fill_f<<<((size_t)N * HC + 255) / 256, 256>>>(agg, 0.f, N * HC);
        k_fill_f<<<(N * NH + 255) / 256, 256>>>(denom, 0.f, N * NH);
        k_fill_i<<<(N * NH + 255) / 256, 256>>>(nmax, (int)ENC_NEG_INF, N * NH);

        // edge passes
        int warps_blocks = (E * 32 + 255) / 256;
        k_scores<<<warps_blocks, 256>>>(eidx, xl, xr, att, ebuf, nmax, E);
        k_exp<<<(E * NH + 255) / 256, 256>>>(eidx, ebuf, nmax, denom, E);
        k_agg<<<warps_blocks, 256>>>(eidx, ebuf, denom, xl, agg, E);

        // head-mean + bias + elu -> h
        k_epi<<<((size_t)N * CD + 255) / 256, 256>>>(agg, bb, hbuf, N);

        hin = hbuf;
        Kin = CD;
    }

    // global mean pool + final linear
    k_fill_f<<<(NG * CD + 255) / 256, 256>>>(gsum, 0.f, NG * CD);
    k_fill_f<<<1, 64>>>(gcnt, 0.f, NG);
    k_pool<<<(N + 63) / 64, 128>>>(hbuf, batch, N);
    k_final<<<(NG * CD + 255) / 256, 256>>>(lin_W, lin_b, (float*)d_out);
}

// round 9
// speedup vs baseline: 2.1747x; 2.1747x over previous
#include <cuda_runtime.h>
#include <cstdint>

#define NN   50000
#define EE   400000
#define NH   4
#define CD   128
#define HC   512
#define NG   64

// ---------------- device scratch ----------------
__device__ float g_xl[(size_t)NN * HC];
__device__ float g_xr[(size_t)NN * HC];
__device__ float g_agg[(size_t)NN * CD];     // head-fused aggregate (25.6 MB)
__device__ float g_h[(size_t)NN * CD];
__device__ float g_e[(size_t)EE * NH];
__device__ int   g_nmax[NN * NH];
__device__ float g_denom[NN * NH];
__device__ float g_gsum[NG * CD];
__device__ float g_gcnt[NG];
__device__ int   g_is64;

// ---------------- helpers ----------------
__device__ __forceinline__ long long ld_idx(const void* p, long long i, int is64) {
    if (is64) return ((const long long*)p)[i];
    return (long long)((const int*)p)[i];
}
__device__ __forceinline__ int enc_f(float f) {
    int i = __float_as_int(f);
    return (i >= 0) ? i : (i ^ 0x7FFFFFFF);
}
__device__ __forceinline__ float dec_f(int i) {
    return __int_as_float((i >= 0) ? i : (i ^ 0x7FFFFFFF));
}
#define ENC_NEG_INF 0x807FFFFF

// vectorized global float reduction (sm_90+): one instruction, 16 bytes
__device__ __forceinline__ void red_add_v4(float* p, float4 v) {
    asm volatile("red.global.add.v4.f32 [%0], {%1, %2, %3, %4};"
                 :: "l"(p), "f"(v.x), "f"(v.y), "f"(v.z), "f"(v.w) : "memory");
}

// ---------------- index dtype detection ----------------
__global__ void k_detect(const unsigned int* __restrict__ w, int npairs) {
    __shared__ int s_any;
    if (threadIdx.x == 0) s_any = 0;
    __syncthreads();
    int any = 0;
    for (int i = threadIdx.x; i < npairs; i += blockDim.x)
        if (w[2 * i + 1] != 0u) any = 1;
    if (any) atomicOr(&s_any, 1);
    __syncthreads();
    if (threadIdx.x == 0) g_is64 = s_any ? 0 : 1;
}

// ---------------- fills ----------------
__global__ void k_fill4(float4* __restrict__ p, float v, int n4) {
    float4 q = make_float4(v, v, v, v);
    for (int i = blockIdx.x * blockDim.x + threadIdx.x; i < n4; i += gridDim.x * blockDim.x)
        p[i] = q;
}
__global__ void k_init_nd(float* __restrict__ denom, int* __restrict__ nmax, int n) {
    int i = blockIdx.x * blockDim.x + threadIdx.x;
    if (i < n) { denom[i] = 0.f; nmax[i] = (int)ENC_NEG_INF; }
}

// ---------------- layer-0 GEMM (K=3): xl and xr in one pass ----------------
__global__ __launch_bounds__(256) void k_gemm3(
    const float* __restrict__ x,
    const float* __restrict__ Wl, const float* __restrict__ bl,
    const float* __restrict__ Wr, const float* __restrict__ br,
    float* __restrict__ xl, float* __restrict__ xr, int N)
{
    __shared__ float s[1536 * 2 + 512 * 2];
    float* sWl = s;          float* sWr = s + 1536;
    float* sbl = s + 3072;   float* sbr = s + 3584;
    for (int i = threadIdx.x; i < 1536; i += 256) { sWl[i] = Wl[i]; sWr[i] = Wr[i]; }
    for (int i = threadIdx.x; i < 512;  i += 256) { sbl[i] = bl[i]; sbr[i] = br[i]; }
    __syncthreads();
    int total = N * 128;   // one float4 of each output per thread-iter
    for (int t = blockIdx.x * blockDim.x + threadIdx.x; t < total; t += gridDim.x * blockDim.x) {
        int n = t >> 7, jv = (t & 127) << 2;
        float x0 = x[n * 3 + 0], x1 = x[n * 3 + 1], x2 = x[n * 3 + 2];
        {
            float4 w0 = *(float4*)&sWl[jv], w1 = *(float4*)&sWl[512 + jv], w2 = *(float4*)&sWl[1024 + jv];
            float4 b = *(float4*)&sbl[jv];
            float4 o;
            o.x = x0 * w0.x + x1 * w1.x + x2 * w2.x + b.x;
            o.y = x0 * w0.y + x1 * w1.y + x2 * w2.y + b.y;
            o.z = x0 * w0.z + x1 * w1.z + x2 * w2.z + b.z;
            o.w = x0 * w0.w + x1 * w1.w + x2 * w2.w + b.w;
            *(float4*)(xl + (size_t)n * HC + jv) = o;
        }
        {
            float4 w0 = *(float4*)&sWr[jv], w1 = *(float4*)&sWr[512 + jv], w2 = *(float4*)&sWr[1024 + jv];
            float4 b = *(float4*)&sbr[jv];
            float4 o;
            o.x = x0 * w0.x + x1 * w1.x + x2 * w2.x + b.x;
            o.y = x0 * w0.y + x1 * w1.y + x2 * w2.y + b.y;
            o.z = x0 * w0.z + x1 * w1.z + x2 * w2.z + b.z;
            o.w = x0 * w0.w + x1 * w1.w + x2 * w2.w + b.w;
            *(float4*)(xr + (size_t)n * HC + jv) = o;
        }
    }
}

// ---------------- K=128, N=512 SGEMM: C = A@B + bias ----------------
// 128x128 tile, BK=16, 256 threads, 8x8 micro (4+4 split), double-buffered.
__global__ __launch_bounds__(256) void k_sgemm128(
    const float* __restrict__ A, const float* __restrict__ B,
    const float* __restrict__ bias, float* __restrict__ C, int M)
{
    __shared__ float As[2][16][128];
    __shared__ float Bs[2][16][128];
    const int bm = blockIdx.y * 128, bn = blockIdx.x * 128;
    const int tid = threadIdx.x;
    const int tr = tid >> 4, tc = tid & 15;
    const int a_row = tid >> 2, a_vc = (tid & 3) << 2;   // A tile 128x16
    const int b_r = tid >> 5, b_vc = (tid & 31) << 2;    // B tile 16x128

    float acc[8][8];
#pragma unroll
    for (int i = 0; i < 8; i++)
#pragma unroll
        for (int j = 0; j < 8; j++) acc[i][j] = 0.f;

#pragma unroll
    for (int t = 0; t < 2; t++) {
        int gm = bm + a_row + 64 * t;
        float4 v = (gm < M) ? *(const float4*)(A + (size_t)gm * 128 + a_vc)
                            : make_float4(0, 0, 0, 0);
        As[0][a_vc + 0][a_row + 64 * t] = v.x;
        As[0][a_vc + 1][a_row + 64 * t] = v.y;
        As[0][a_vc + 2][a_row + 64 * t] = v.z;
        As[0][a_vc + 3][a_row + 64 * t] = v.w;
        *(float4*)&Bs[0][b_r + 8 * t][b_vc] =
            *(const float4*)(B + (size_t)(b_r + 8 * t) * 512 + bn + b_vc);
    }
    __syncthreads();

    int buf = 0;
    for (int k0 = 16; k0 <= 128; k0 += 16) {
        float4 pa[2], pb[2];
        if (k0 < 128) {
#pragma unroll
            for (int t = 0; t < 2; t++) {
                int gm = bm + a_row + 64 * t;
                pa[t] = (gm < M) ? *(const float4*)(A + (size_t)gm * 128 + k0 + a_vc)
                                 : make_float4(0, 0, 0, 0);
                pb[t] = *(const float4*)(B + (size_t)(k0 + b_r + 8 * t) * 512 + bn + b_vc);
            }
        }
#pragma unroll
        for (int kk = 0; kk < 16; kk++) {
            float4 a0 = *(const float4*)&As[buf][kk][tr * 4];
            float4 a1 = *(const float4*)&As[buf][kk][64 + tr * 4];
            float4 b0 = *(const float4*)&Bs[buf][kk][tc * 4];
            float4 b1 = *(const float4*)&Bs[buf][kk][64 + tc * 4];
            float a[8] = {a0.x, a0.y, a0.z, a0.w, a1.x, a1.y, a1.z, a1.w};
            float b[8] = {b0.x, b0.y, b0.z, b0.w, b1.x, b1.y, b1.z, b1.w};
#pragma unroll
            for (int i = 0; i < 8; i++)
#pragma unroll
                for (int j = 0; j < 8; j++) acc[i][j] += a[i] * b[j];
        }
        if (k0 < 128) {
#pragma unroll
            for (int t = 0; t < 2; t++) {
                As[buf ^ 1][a_vc + 0][a_row + 64 * t] = pa[t].x;
                As[buf ^ 1][a_vc + 1][a_row + 64 * t] = pa[t].y;
                As[buf ^ 1][a_vc + 2][a_row + 64 * t] = pa[t].z;
                As[buf ^ 1][a_vc + 3][a_row + 64 * t] = pa[t].w;
                *(float4*)&Bs[buf ^ 1][b_r + 8 * t][b_vc] = pb[t];
            }
            __syncthreads();
            buf ^= 1;
        }
    }

#pragma unroll
    for (int half = 0; half < 2; half++) {
#pragma unroll
        for (int i = 0; i < 4; i++) {
            int gm = bm + half * 64 + tr * 4 + i;
            if (gm >= M) continue;
#pragma unroll
            for (int jh = 0; jh < 2; jh++) {
                int gn = bn + jh * 64 + tc * 4;
                float4 r;
                r.x = acc[half * 4 + i][jh * 4 + 0] + bias[gn + 0];
                r.y = acc[half * 4 + i][jh * 4 + 1] + bias[gn + 1];
                r.z = acc[half * 4 + i][jh * 4 + 2] + bias[gn + 2];
                r.w = acc[half * 4 + i][jh * 4 + 3] + bias[gn + 3];
                *(float4*)(C + (size_t)gm * 512 + gn) = r;
            }
        }
    }
}

// ---------------- edge pass 1: scores + segment max ----------------
// one warp per edge; per head h: e = leaky_relu(xl[s]+xr[d]) . att[h]
__global__ void k_scores(const void* __restrict__ eidx,
                         const float* __restrict__ xl, const float* __restrict__ xr,
                         const float* __restrict__ att,
                         float* __restrict__ eout, int* __restrict__ nmax, int E)
{
    int gw = (blockIdx.x * blockDim.x + threadIdx.x) >> 5;
    int lane = threadIdx.x & 31;
    if (gw >= E) return;
    int is64 = g_is64;
    long long s = ld_idx(eidx, gw, is64);
    long long d = ld_idx(eidx, (long long)E + gw, is64);
    const float4* xls = (const float4*)(xl + (size_t)s * HC);
    const float4* xrd = (const float4*)(xr + (size_t)d * HC);
    const float4* at4 = (const float4*)att;
#pragma unroll
    for (int h = 0; h < NH; h++) {
        float4 a = xls[h * 32 + lane];
        float4 b = xrd[h * 32 + lane];
        float4 w = at4[h * 32 + lane];
        float m0 = a.x + b.x; m0 = m0 > 0.f ? m0 : 0.2f * m0;
        float m1 = a.y + b.y; m1 = m1 > 0.f ? m1 : 0.2f * m1;
        float m2 = a.z + b.z; m2 = m2 > 0.f ? m2 : 0.2f * m2;
        float m3 = a.w + b.w; m3 = m3 > 0.f ? m3 : 0.2f * m3;
        float sum = m0 * w.x + m1 * w.y + m2 * w.z + m3 * w.w;
#pragma unroll
        for (int o = 16; o > 0; o >>= 1) sum += __shfl_xor_sync(0xffffffffu, sum, o);
        // after butterfly every lane has the total; lane h owns head h's writes
        if (lane == h) {
            eout[(size_t)gw * NH + h] = sum;
            atomicMax(&nmax[(int)d * NH + h], enc_f(sum));
        }
    }
}

// ---------------- edge pass 2: exp + segment sum ----------------
__global__ void k_exp(const void* __restrict__ eidx, float* __restrict__ ebuf,
                      const int* __restrict__ nmax, float* __restrict__ denom, int E)
{
    int t = blockIdx.x * blockDim.x + threadIdx.x;
    if (t >= E * NH) return;
    int edge = t >> 2, h = t & 3;
    int is64 = g_is64;
    long long d = ld_idx(eidx, (long long)E + edge, is64);
    float mx = dec_f(nmax[(int)d * NH + h]);
    float ee = __expf(ebuf[t] - mx);
    ebuf[t] = ee;
    atomicAdd(&denom[(int)d * NH + h], ee);
}

// ---------------- edge pass 3: head-fused weighted aggregation ----------------
// per edge, 128 outputs: sum_h alpha_h * xl[s, h, c]; one v4 RED per lane.
__global__ void k_agg(const void* __restrict__ eidx, const float* __restrict__ ebuf,
                      const float* __restrict__ denom, const float* __restrict__ xl,
                      float* __restrict__ agg, int E)
{
    int gw = (blockIdx.x * blockDim.x + threadIdx.x) >> 5;
    int lane = threadIdx.x & 31;
    if (gw >= E) return;
    int is64 = g_is64;
    long long s = ld_idx(eidx, gw, is64);
    long long d = ld_idx(eidx, (long long)E + gw, is64);
    float av = 0.f;
    if (lane < 4) av = ebuf[(size_t)gw * NH + lane] / denom[(int)d * NH + lane];
    float al0 = __shfl_sync(0xffffffffu, av, 0);
    float al1 = __shfl_sync(0xffffffffu, av, 1);
    float al2 = __shfl_sync(0xffffffffu, av, 2);
    float al3 = __shfl_sync(0xffffffffu, av, 3);
    const float4* xs = (const float4*)(xl + (size_t)s * HC);
    float4 v0 = xs[lane], v1 = xs[32 + lane], v2 = xs[64 + lane], v3 = xs[96 + lane];
    float4 r;
    r.x = al0 * v0.x + al1 * v1.x + al2 * v2.x + al3 * v3.x;
    r.y = al0 * v0.y + al1 * v1.y + al2 * v2.y + al3 * v3.y;
    r.z = al0 * v0.z + al1 * v1.z + al2 * v2.z + al3 * v3.z;
    r.w = al0 * v0.w + al1 * v1.w + al2 * v2.w + al3 * v3.w;
    red_add_v4(agg + (size_t)d * CD + lane * 4, r);
}

// ---------------- epilogue: head mean + bias + elu ----------------
__global__ void k_epi(const float* __restrict__ agg, const float* __restrict__ bias,
                      float* __restrict__ hout, int N)
{
    int t = blockIdx.x * blockDim.x + threadIdx.x;
    if (t >= N * CD) return;
    int c = t & 127;
    float v = 0.25f * agg[t] + bias[c];
    hout[t] = v > 0.f ? v : (expf(v) - 1.f);
}

// ---------------- global mean pool (batch sorted) ----------------
__global__ void k_pool(const float* __restrict__ h, const void* __restrict__ batch, int N)
{
    int c = threadIdx.x;
    int n0 = blockIdx.x * 64;
    int n1 = n0 + 64; if (n1 > N) n1 = N;
    int is64 = g_is64;
    long long cur = -1; float acc = 0.f, cnt = 0.f;
    for (int n = n0; n < n1; n++) {
        long long g = ld_idx(batch, n, is64);
        if (g != cur) {
            if (cur >= 0) {
                atomicAdd(&g_gsum[(int)cur * CD + c], acc);
                if (c == 0) atomicAdd(&g_gcnt[(int)cur], cnt);
            }
            cur = g; acc = 0.f; cnt = 0.f;
        }
        acc += h[(size_t)n * CD + c];
        cnt += 1.f;
    }
    if (cur >= 0) {
        atomicAdd(&g_gsum[(int)cur * CD + c], acc);
        if (c == 0) atomicAdd(&g_gcnt[(int)cur], cnt);
    }
}

// ---------------- final linear ----------------
__global__ void k_final(const float* __restrict__ W, const float* __restrict__ b,
                        float* __restrict__ out)
{
    int t = blockIdx.x * blockDim.x + threadIdx.x;
    if (t >= NG * CD) return;
    int g = t >> 7, z = t & 127;
    float inv = 1.f / fmaxf(g_gcnt[g], 1.f);
    float acc = 0.f;
#pragma unroll 8
    for (int c = 0; c < CD; c++)
        acc += g_gsum[g * CD + c] * W[c * CD + z];
    out[t] = acc * inv + b[z];
}

// ---------------- host orchestration ----------------
extern "C" void kernel_launch(void* const* d_in, const int* in_sizes, int n_in,
                              void* d_out, int out_size)
{
    const float* x     = (const float*)d_in[0];
    const void*  eidx  = d_in[1];
    const void*  batch = d_in[2];
    const float* lin_W = (const float*)d_in[21];
    const float* lin_b = (const float*)d_in[22];

    const int N = in_sizes[2];
    const int E = in_sizes[1] / 2;

    float *xl, *xr, *agg, *hbuf, *ebuf, *denom, *gsum, *gcnt; int* nmax;
    cudaGetSymbolAddress((void**)&xl,    g_xl);
    cudaGetSymbolAddress((void**)&xr,    g_xr);
    cudaGetSymbolAddress((void**)&agg,   g_agg);
    cudaGetSymbolAddress((void**)&hbuf,  g_h);
    cudaGetSymbolAddress((void**)&ebuf,  g_e);
    cudaGetSymbolAddress((void**)&nmax,  g_nmax);
    cudaGetSymbolAddress((void**)&denom, g_denom);
    cudaGetSymbolAddress((void**)&gsum,  g_gsum);
    cudaGetSymbolAddress((void**)&gcnt,  g_gcnt);

    k_detect<<<1, 256>>>((const unsigned int*)eidx, 4096);

    for (int l = 0; l < 3; l++) {
        const float* Wl  = (const float*)d_in[3 + 6 * l + 0];
        const float* bl  = (const float*)d_in[3 + 6 * l + 1];
        const float* Wr  = (const float*)d_in[3 + 6 * l + 2];
        const float* br  = (const float*)d_in[3 + 6 * l + 3];
        const float* att = (const float*)d_in[3 + 6 * l + 4];
        const float* bb  = (const float*)d_in[3 + 6 * l + 5];

        if (l == 0) {
            k_gemm3<<<2048, 256>>>(x, Wl, bl, Wr, br, xl, xr, N);
        } else {
            dim3 gg(4, (N + 127) / 128);
            k_sgemm128<<<gg, 256>>>(hbuf, Wl, bl, xl, N);
            k_sgemm128<<<gg, 256>>>(hbuf, Wr, br, xr, N);
        }

        k_fill4<<<1024, 256>>>((float4*)agg, 0.f, N * CD / 4);
        k_init_nd<<<(N * NH + 255) / 256, 256>>>(denom, nmax, N * NH);

        int warps_blocks = (E * 32 + 255) / 256;
        k_scores<<<warps_blocks, 256>>>(eidx, xl, xr, att, ebuf, nmax, E);
        k_exp<<<(E * NH + 255) / 256, 256>>>(eidx, ebuf, nmax, denom, E);
        k_agg<<<warps_blocks, 256>>>(eidx, ebuf, denom, xl, agg, E);

        k_epi<<<((size_t)N * CD + 255) / 256, 256>>>(agg, bb, hbuf, N);
    }

    k_fill4<<<8, 256>>>((float4*)gsum, 0.f, NG * CD / 4);
    k_fill4<<<1, 16>>>((float4*)gcnt, 0.f, NG / 4);
    k_pool<<<(N + 63) / 64, 128>>>(hbuf, batch, N);
    k_final<<<(NG * CD + 255) / 256, 256>>>(lin_W, lin_b, (float*)d_out);
}

// round 11
// speedup vs baseline: 2.7350x; 1.2577x over previous
#include <cuda_runtime.h>
#include <cuda_bf16.h>
#include <cstdint>

#define NN   50000
#define EE   400000
#define NH   4
#define CD   128
#define HC   512
#define NG   64
#define NT_M 391          // ceil(50000/128) M-tiles
#define TILE_ELEMS 16384  // 128x128 bf16 tile

// ---------------- device scratch ----------------
__device__ float g_xl[(size_t)NN * HC];
__device__ float g_xr[(size_t)NN * HC];
__device__ float g_agg[(size_t)NN * CD];
__device__ float g_h[(size_t)NN * CD];
__device__ float g_e[(size_t)EE * NH];
__device__ int   g_nmax[NN * NH];
__device__ float g_denom[NN * NH];
__device__ float g_gsum[NG * CD];
__device__ float g_gcnt[NG];
__device__ int   g_is64;
// row-major bf16 hi/lo operands for tensor-core GEMM (zero-init covers tail rows)
__device__ __align__(16) unsigned short g_ahi[(size_t)NT_M * TILE_ELEMS];
__device__ __align__(16) unsigned short g_alo[(size_t)NT_M * TILE_ELEMS];
__device__ __align__(16) unsigned short g_bhi[2 * 128 * 512];   // [side][k][n]
__device__ __align__(16) unsigned short g_blo[2 * 128 * 512];

// ---------------- generic helpers ----------------
__device__ __forceinline__ long long ld_idx(const void* p, long long i, int is64) {
    if (is64) return ((const long long*)p)[i];
    return (long long)((const int*)p)[i];
}
__device__ __forceinline__ int enc_f(float f) {
    int i = __float_as_int(f);
    return (i >= 0) ? i : (i ^ 0x7FFFFFFF);
}
__device__ __forceinline__ float dec_f(int i) {
    return __int_as_float((i >= 0) ? i : (i ^ 0x7FFFFFFF));
}
#define ENC_NEG_INF 0x807FFFFF

__device__ __forceinline__ void red_add_v4(float* p, float4 v) {
    asm volatile("red.global.add.v4.f32 [%0], {%1, %2, %3, %4};"
                 :: "l"(p), "f"(v.x), "f"(v.y), "f"(v.z), "f"(v.w) : "memory");
}

// ---------------- mma.sync building blocks (sm_80+, no sm_103a features) ----------------
__device__ __forceinline__ uint32_t smem_u32(const void* p) {
    uint32_t a;
    asm("{ .reg .u64 t; cvta.to.shared.u64 t, %1; cvt.u32.u64 %0, t; }" : "=r"(a) : "l"(p));
    return a;
}
__device__ __forceinline__ void ldsm_x4(uint32_t* r, uint32_t addr) {
    asm volatile("ldmatrix.sync.aligned.m8n8.x4.shared.b16 {%0,%1,%2,%3}, [%4];"
                 : "=r"(r[0]), "=r"(r[1]), "=r"(r[2]), "=r"(r[3]) : "r"(addr));
}
__device__ __forceinline__ void ldsm_x4_t(uint32_t* r, uint32_t addr) {
    asm volatile("ldmatrix.sync.aligned.m8n8.x4.trans.shared.b16 {%0,%1,%2,%3}, [%4];"
                 : "=r"(r[0]), "=r"(r[1]), "=r"(r[2]), "=r"(r[3]) : "r"(addr));
}
__device__ __forceinline__ void mma_bf16(float* d, const uint32_t* a, const uint32_t* b) {
    asm volatile("mma.sync.aligned.m16n8k16.row.col.f32.bf16.bf16.f32 "
                 "{%0,%1,%2,%3}, {%4,%5,%6,%7}, {%8,%9}, {%0,%1,%2,%3};"
                 : "+f"(d[0]), "+f"(d[1]), "+f"(d[2]), "+f"(d[3])
                 : "r"(a[0]), "r"(a[1]), "r"(a[2]), "r"(a[3]), "r"(b[0]), "r"(b[1]));
}

// ---------------- index dtype detection ----------------
__global__ void k_detect(const unsigned int* __restrict__ w, int npairs) {
    __shared__ int s_any;
    if (threadIdx.x == 0) s_any = 0;
    __syncthreads();
    int any = 0;
    for (int i = threadIdx.x; i < npairs; i += blockDim.x)
        if (w[2 * i + 1] != 0u) any = 1;
    if (any) atomicOr(&s_any, 1);
    __syncthreads();
    if (threadIdx.x == 0) g_is64 = s_any ? 0 : 1;
}

// ---------------- fills ----------------
__global__ void k_fill4(float4* __restrict__ p, float v, int n4) {
    float4 q = make_float4(v, v, v, v);
    for (int i = blockIdx.x * blockDim.x + threadIdx.x; i < n4; i += gridDim.x * blockDim.x)
        p[i] = q;
}
__global__ void k_init_nd(float* __restrict__ denom, int* __restrict__ nmax, int n) {
    int i = blockIdx.x * blockDim.x + threadIdx.x;
    if (i < n) { denom[i] = 0.f; nmax[i] = (int)ENC_NEG_INF; }
}

// ---------------- layer-0 GEMM (K=3): xl and xr in one pass ----------------
__global__ __launch_bounds__(256) void k_gemm3(
    const float* __restrict__ x,
    const float* __restrict__ Wl, const float* __restrict__ bl,
    const float* __restrict__ Wr, const float* __restrict__ br,
    float* __restrict__ xl, float* __restrict__ xr, int N)
{
    __shared__ float s[1536 * 2 + 512 * 2];
    float* sWl = s;          float* sWr = s + 1536;
    float* sbl = s + 3072;   float* sbr = s + 3584;
    for (int i = threadIdx.x; i < 1536; i += 256) { sWl[i] = Wl[i]; sWr[i] = Wr[i]; }
    for (int i = threadIdx.x; i < 512;  i += 256) { sbl[i] = bl[i]; sbr[i] = br[i]; }
    __syncthreads();
    int total = N * 128;
    for (int t = blockIdx.x * blockDim.x + threadIdx.x; t < total; t += gridDim.x * blockDim.x) {
        int n = t >> 7, jv = (t & 127) << 2;
        float x0 = x[n * 3 + 0], x1 = x[n * 3 + 1], x2 = x[n * 3 + 2];
        {
            float4 w0 = *(float4*)&sWl[jv], w1 = *(float4*)&sWl[512 + jv], w2 = *(float4*)&sWl[1024 + jv];
            float4 b = *(float4*)&sbl[jv];
            float4 o;
            o.x = x0 * w0.x + x1 * w1.x + x2 * w2.x + b.x;
            o.y = x0 * w0.y + x1 * w1.y + x2 * w2.y + b.y;
            o.z = x0 * w0.z + x1 * w1.z + x2 * w2.z + b.z;
            o.w = x0 * w0.w + x1 * w1.w + x2 * w2.w + b.w;
            *(float4*)(xl + (size_t)n * HC + jv) = o;
        }
        {
            float4 w0 = *(float4*)&sWr[jv], w1 = *(float4*)&sWr[512 + jv], w2 = *(float4*)&sWr[1024 + jv];
            float4 b = *(float4*)&sbr[jv];
            float4 o;
            o.x = x0 * w0.x + x1 * w1.x + x2 * w2.x + b.x;
            o.y = x0 * w0.y + x1 * w1.y + x2 * w2.y + b.y;
            o.z = x0 * w0.z + x1 * w1.z + x2 * w2.z + b.z;
            o.w = x0 * w0.w + x1 * w1.w + x2 * w2.w + b.w;
            *(float4*)(xr + (size_t)n * HC + jv) = o;
        }
    }
}

// ---------------- weight prep: W[128,512] -> hi/lo bf16 row-major ----------------
__global__ void k_prep_w(const float* __restrict__ Wl, const float* __restrict__ Wr,
                         unsigned short* __restrict__ bhi, unsigned short* __restrict__ blo)
{
    int t = blockIdx.x * blockDim.x + threadIdx.x;   // 2 * 65536/8 = 16384
    if (t >= 16384) return;
    int side = t >> 13;
    int idx8 = (t & 8191) << 3;                      // element offset within [128][512]
    const float* W = side ? Wr : Wl;
    __align__(16) __nv_bfloat16 hi[8], lo[8];
#pragma unroll
    for (int j = 0; j < 8; j++) {
        float v = W[idx8 + j];
        __nv_bfloat16 h = __float2bfloat16(v);
        hi[j] = h;
        lo[j] = __float2bfloat16(v - __bfloat162float(h));
    }
    *(uint4*)(bhi + side * 65536 + idx8) = *(uint4*)hi;
    *(uint4*)(blo + side * 65536 + idx8) = *(uint4*)lo;
}

// ---------------- tensor-core GEMM via mma.sync: [xl|xr] = h @ [Wl|Wr] + bias ----------------
// grid (8, NT_M): blockIdx.x = side*4 + ntile. 256 thr = 8 warps (4m x 2n), warp = 32x64.
// smem: Ahi | Alo | Bhi | Blo, 32 KB each. Layout: half (k-half for A, n-half for B) of
// 128 rows x 128 B, 16B-granule xor-swizzled by row&7 for conflict-free ldmatrix.
__global__ __launch_bounds__(256) void k_mma(
    const unsigned short* __restrict__ ahi, const unsigned short* __restrict__ alo,
    const unsigned short* __restrict__ bhi_g, const unsigned short* __restrict__ blo_g,
    const float* __restrict__ bl, const float* __restrict__ br,
    float* __restrict__ xl, float* __restrict__ xr, int M)
{
    extern __shared__ __align__(16) char smem[];
    const int mt = blockIdx.y, nt8 = blockIdx.x;
    const int side = nt8 >> 2, ntile = nt8 & 3;
    const int tid = threadIdx.x, wid = tid >> 5, lane = tid & 31;

    // ---- global -> swizzled smem (one shot, K=128 fits entirely) ----
    {
        const char* gA0 = (const char*)ahi + (size_t)mt * 32768;
        const char* gA1 = (const char*)alo + (size_t)mt * 32768;
        const char* gB0 = (const char*)bhi_g + (size_t)side * 131072;
        const char* gB1 = (const char*)blo_g + (size_t)side * 131072;
#pragma unroll 2
        for (int i = tid; i < 2048; i += 256) {
            int r = i >> 4, g = i & 15;
            int half = g >> 3, gg = g & 7;
            int dst = half * 16384 + r * 128 + ((gg * 16) ^ ((r & 7) << 4));
            *(uint4*)(smem + dst)          = *(const uint4*)(gA0 + r * 256 + g * 16);
            *(uint4*)(smem + 32768 + dst)  = *(const uint4*)(gA1 + r * 256 + g * 16);
            // B: r = k row; source row is 1024 B (512 bf16), take this ntile's 256 B
            *(uint4*)(smem + 65536 + dst)  = *(const uint4*)(gB0 + r * 1024 + ntile * 256 + g * 16);
            *(uint4*)(smem + 98304 + dst)  = *(const uint4*)(gB1 + r * 1024 + ntile * 256 + g * 16);
        }
    }
    __syncthreads();

    const uint32_t sbase = smem_u32(smem);
    const int m0 = (wid >> 1) * 32, n0 = (wid & 1) * 64;

    float acc[2][8][4];
#pragma unroll
    for (int i = 0; i < 2; i++)
#pragma unroll
        for (int j = 0; j < 8; j++)
#pragma unroll
            for (int q = 0; q < 4; q++) acc[i][j][q] = 0.f;

#pragma unroll
    for (int ks = 0; ks < 8; ks++) {
        // A fragments (hi & lo) for both 16-row tiles
        uint32_t aH[2][4], aL[2][4];
        {
            int cb = ((ks & 3) << 5) + ((lane >> 4) << 4);
#pragma unroll
            for (int mt2 = 0; mt2 < 2; mt2++) {
                int rr = m0 + mt2 * 16 + (lane & 15);
                uint32_t ad = sbase + (ks >> 2) * 16384 + rr * 128 + (cb ^ ((rr & 7) << 4));
                ldsm_x4(aH[mt2], ad);
                ldsm_x4(aL[mt2], ad + 32768);
            }
        }
        int rowk = ks * 16 + (lane & 15);
        int swk = (rowk & 7) << 4;
#pragma unroll
        for (int nc = 0; nc < 4; nc++) {
            int nb = n0 + nc * 16;
            uint32_t cbyte = ((nb & 63) << 1) + ((lane >> 4) << 4);
            uint32_t ad = sbase + 65536 + (nb >> 6) * 16384 + rowk * 128 + (cbyte ^ swk);
            uint32_t bH[4], bL[4];
            ldsm_x4_t(bH, ad);
            ldsm_x4_t(bL, ad + 32768);
#pragma unroll
            for (int mt2 = 0; mt2 < 2; mt2++) {
#pragma unroll
                for (int j = 0; j < 2; j++) {
                    float* d = acc[mt2][nc * 2 + j];
                    mma_bf16(d, aH[mt2], bH + 2 * j);   // hi*hi
                    mma_bf16(d, aH[mt2], bL + 2 * j);   // hi*lo
                    mma_bf16(d, aL[mt2], bH + 2 * j);   // lo*hi
                }
            }
        }
    }

    // ---- epilogue: + bias, fp32 store ----
    const float* bias = side ? br : bl;
    float* out = side ? xr : xl;
    const int rbase = mt * 128 + m0;
#pragma unroll
    for (int mt2 = 0; mt2 < 2; mt2++) {
        int r0 = rbase + mt2 * 16 + (lane >> 2);
#pragma unroll
        for (int nt = 0; nt < 8; nt++) {
            int c = ntile * 128 + n0 + nt * 8 + (lane & 3) * 2;
            float2 b2 = *(const float2*)(bias + c);
            if (r0 < M) {
                float2 v = make_float2(acc[mt2][nt][0] + b2.x, acc[mt2][nt][1] + b2.y);
                *(float2*)(out + (size_t)r0 * 512 + c) = v;
            }
            if (r0 + 8 < M) {
                float2 v = make_float2(acc[mt2][nt][2] + b2.x, acc[mt2][nt][3] + b2.y);
                *(float2*)(out + (size_t)(r0 + 8) * 512 + c) = v;
            }
        }
    }
}

// ---------------- edge pass 1: scores + segment max ----------------
__global__ void k_scores(const void* __restrict__ eidx,
                         const float* __restrict__ xl, const float* __restrict__ xr,
                         const float* __restrict__ att,
                         float* __restrict__ eout, int* __restrict__ nmax, int E)
{
    int gw = (blockIdx.x * blockDim.x + threadIdx.x) >> 5;
    int lane = threadIdx.x & 31;
    if (gw >= E) return;
    int is64 = g_is64;
    long long s = ld_idx(eidx, gw, is64);
    long long d = ld_idx(eidx, (long long)E + gw, is64);
    const float4* xls = (const float4*)(xl + (size_t)s * HC);
    const float4* xrd = (const float4*)(xr + (size_t)d * HC);
    const float4* at4 = (const float4*)att;
#pragma unroll
    for (int h = 0; h < NH; h++) {
        float4 a = xls[h * 32 + lane];
        float4 b = xrd[h * 32 + lane];
        float4 w = at4[h * 32 + lane];
        float m0 = a.x + b.x; m0 = m0 > 0.f ? m0 : 0.2f * m0;
        float m1 = a.y + b.y; m1 = m1 > 0.f ? m1 : 0.2f * m1;
        float m2 = a.z + b.z; m2 = m2 > 0.f ? m2 : 0.2f * m2;
        float m3 = a.w + b.w; m3 = m3 > 0.f ? m3 : 0.2f * m3;
        float sum = m0 * w.x + m1 * w.y + m2 * w.z + m3 * w.w;
#pragma unroll
        for (int o = 16; o > 0; o >>= 1) sum += __shfl_xor_sync(0xffffffffu, sum, o);
        if (lane == h) {
            eout[(size_t)gw * NH + h] = sum;
            atomicMax(&nmax[(int)d * NH + h], enc_f(sum));
        }
    }
}

// ---------------- edge pass 2: exp + segment sum ----------------
__global__ void k_exp(const void* __restrict__ eidx, float* __restrict__ ebuf,
                      const int* __restrict__ nmax, float* __restrict__ denom, int E)
{
    int t = blockIdx.x * blockDim.x + threadIdx.x;
    if (t >= E * NH) return;
    int edge = t >> 2, h = t & 3;
    int is64 = g_is64;
    long long d = ld_idx(eidx, (long long)E + edge, is64);
    float mx = dec_f(nmax[(int)d * NH + h]);
    float ee = __expf(ebuf[t] - mx);
    ebuf[t] = ee;
    atomicAdd(&denom[(int)d * NH + h], ee);
}

// ---------------- edge pass 3: head-fused weighted aggregation ----------------
__global__ void k_agg(const void* __restrict__ eidx, const float* __restrict__ ebuf,
                      const float* __restrict__ denom, const float* __restrict__ xl,
                      float* __restrict__ agg, int E)
{
    int gw = (blockIdx.x * blockDim.x + threadIdx.x) >> 5;
    int lane = threadIdx.x & 31;
    if (gw >= E) return;
    int is64 = g_is64;
    long long s = ld_idx(eidx, gw, is64);
    long long d = ld_idx(eidx, (long long)E + gw, is64);
    float av = 0.f;
    if (lane < 4) av = ebuf[(size_t)gw * NH + lane] / denom[(int)d * NH + lane];
    float al0 = __shfl_sync(0xffffffffu, av, 0);
    float al1 = __shfl_sync(0xffffffffu, av, 1);
    float al2 = __shfl_sync(0xffffffffu, av, 2);
    float al3 = __shfl_sync(0xffffffffu, av, 3);
    const float4* xs = (const float4*)(xl + (size_t)s * HC);
    float4 v0 = xs[lane], v1 = xs[32 + lane], v2 = xs[64 + lane], v3 = xs[96 + lane];
    float4 r;
    r.x = al0 * v0.x + al1 * v1.x + al2 * v2.x + al3 * v3.x;
    r.y = al0 * v0.y + al1 * v1.y + al2 * v2.y + al3 * v3.y;
    r.z = al0 * v0.z + al1 * v1.z + al2 * v2.z + al3 * v3.z;
    r.w = al0 * v0.w + al1 * v1.w + al2 * v2.w + al3 * v3.w;
    red_add_v4(agg + (size_t)d * CD + lane * 4, r);
}

// ---------------- epilogue: head mean + bias + elu -> h + next-layer hi/lo ----------------
__global__ void k_epi(const float* __restrict__ agg, const float* __restrict__ bias,
                      float* __restrict__ hout,
                      unsigned short* __restrict__ ahi, unsigned short* __restrict__ alo, int N)
{
    int t = blockIdx.x * blockDim.x + threadIdx.x;   // N*16 threads, 8 elems each
    if (t >= N * 16) return;
    int n = t >> 4, c0 = (t & 15) << 3;
    float4 a0 = *(const float4*)(agg + (size_t)n * CD + c0);
    float4 a1 = *(const float4*)(agg + (size_t)n * CD + c0 + 4);
    float4 b0 = *(const float4*)(bias + c0);
    float4 b1 = *(const float4*)(bias + c0 + 4);
    float v[8];
    v[0] = 0.25f * a0.x + b0.x; v[1] = 0.25f * a0.y + b0.y;
    v[2] = 0.25f * a0.z + b0.z; v[3] = 0.25f * a0.w + b0.w;
    v[4] = 0.25f * a1.x + b1.x; v[5] = 0.25f * a1.y + b1.y;
    v[6] = 0.25f * a1.z + b1.z; v[7] = 0.25f * a1.w + b1.w;
    __align__(16) __nv_bfloat16 hi[8], lo[8];
#pragma unroll
    for (int j = 0; j < 8; j++) {
        float e = v[j] > 0.f ? v[j] : (expf(v[j]) - 1.f);
        v[j] = e;
        __nv_bfloat16 h = __float2bfloat16(e);
        hi[j] = h;
        lo[j] = __float2bfloat16(e - __bfloat162float(h));
    }
    *(float4*)(hout + (size_t)n * CD + c0)     = make_float4(v[0], v[1], v[2], v[3]);
    *(float4*)(hout + (size_t)n * CD + c0 + 4) = make_float4(v[4], v[5], v[6], v[7]);
    *(uint4*)(ahi + (size_t)n * CD + c0) = *(uint4*)hi;
    *(uint4*)(alo + (size_t)n * CD + c0) = *(uint4*)lo;
}

// ---------------- global mean pool (batch sorted) ----------------
__global__ void k_pool(const float* __restrict__ h, const void* __restrict__ batch, int N)
{
    int c = threadIdx.x;
    int n0 = blockIdx.x * 64;
    int n1 = n0 + 64; if (n1 > N) n1 = N;
    int is64 = g_is64;
    long long cur = -1; float acc = 0.f, cnt = 0.f;
    for (int n = n0; n < n1; n++) {
        long long g = ld_idx(batch, n, is64);
        if (g != cur) {
            if (cur >= 0) {
                atomicAdd(&g_gsum[(int)cur * CD + c], acc);
                if (c == 0) atomicAdd(&g_gcnt[(int)cur], cnt);
            }
            cur = g; acc = 0.f; cnt = 0.f;
        }
        acc += h[(size_t)n * CD + c];
        cnt += 1.f;
    }
    if (cur >= 0) {
        atomicAdd(&g_gsum[(int)cur * CD + c], acc);
        if (c == 0) atomicAdd(&g_gcnt[(int)cur], cnt);
    }
}

// ---------------- final linear ----------------
__global__ void k_final(const float* __restrict__ W, const float* __restrict__ b,
                        float* __restrict__ out)
{
    int t = blockIdx.x * blockDim.x + threadIdx.x;
    if (t >= NG * CD) return;
    int g = t >> 7, z = t & 127;
    float inv = 1.f / fmaxf(g_gcnt[g], 1.f);
    float acc = 0.f;
#pragma unroll 8
    for (int c = 0; c < CD; c++)
        acc += g_gsum[g * CD + c] * W[c * CD + z];
    out[t] = acc * inv + b[z];
}

// ---------------- host orchestration ----------------
extern "C" void kernel_launch(void* const* d_in, const int* in_sizes, int n_in,
                              void* d_out, int out_size)
{
    const float* x     = (const float*)d_in[0];
    const void*  eidx  = d_in[1];
    const void*  batch = d_in[2];
    const float* lin_W = (const float*)d_in[21];
    const float* lin_b = (const float*)d_in[22];

    const int N = in_sizes[2];
    const int E = in_sizes[1] / 2;

    float *xl, *xr, *agg, *hbuf, *ebuf, *denom, *gsum, *gcnt; int* nmax;
    unsigned short *ahi, *alo, *bhi, *blo;
    cudaGetSymbolAddress((void**)&xl,    g_xl);
    cudaGetSymbolAddress((void**)&xr,    g_xr);
    cudaGetSymbolAddress((void**)&agg,   g_agg);
    cudaGetSymbolAddress((void**)&hbuf,  g_h);
    cudaGetSymbolAddress((void**)&ebuf,  g_e);
    cudaGetSymbolAddress((void**)&nmax,  g_nmax);
    cudaGetSymbolAddress((void**)&denom, g_denom);
    cudaGetSymbolAddress((void**)&gsum,  g_gsum);
    cudaGetSymbolAddress((void**)&gcnt,  g_gcnt);
    cudaGetSymbolAddress((void**)&ahi,   g_ahi);
    cudaGetSymbolAddress((void**)&alo,   g_alo);
    cudaGetSymbolAddress((void**)&bhi,   g_bhi);
    cudaGetSymbolAddress((void**)&blo,   g_blo);

    const int MMA_SMEM = 131072;
    cudaFuncSetAttribute(k_mma, cudaFuncAttributeMaxDynamicSharedMemorySize, MMA_SMEM);

    k_detect<<<1, 256>>>((const unsigned int*)eidx, 4096);

    for (int l = 0; l < 3; l++) {
        const float* Wl  = (const float*)d_in[3 + 6 * l + 0];
        const float* bl  = (const float*)d_in[3 + 6 * l + 1];
        const float* Wr  = (const float*)d_in[3 + 6 * l + 2];
        const float* br  = (const float*)d_in[3 + 6 * l + 3];
        const float* att = (const float*)d_in[3 + 6 * l + 4];
        const float* bb  = (const float*)d_in[3 + 6 * l + 5];

        if (l == 0) {
            k_gemm3<<<2048, 256>>>(x, Wl, bl, Wr, br, xl, xr, N);
        } else {
            k_prep_w<<<64, 256>>>(Wl, Wr, bhi, blo);
            dim3 gg(8, NT_M);
            k_mma<<<gg, 256, MMA_SMEM>>>(ahi, alo, bhi, blo, bl, br, xl, xr, N);
        }

        k_fill4<<<1024, 256>>>((float4*)agg, 0.f, N * CD / 4);
        k_init_nd<<<(N * NH + 255) / 256, 256>>>(denom, nmax, N * NH);

        int warps_blocks = (E * 32 + 255) / 256;
        k_scores<<<warps_blocks, 256>>>(eidx, xl, xr, att, ebuf, nmax, E);
        k_exp<<<(E * NH + 255) / 256, 256>>>(eidx, ebuf, nmax, denom, E);
        k_agg<<<warps_blocks, 256>>>(eidx, ebuf, denom, xl, agg, E);

        k_epi<<<(N * 16 + 255) / 256, 256>>>(agg, bb, hbuf, ahi, alo, N);
    }

    k_fill4<<<8, 256>>>((float4*)gsum, 0.f, NG * CD / 4);
    k_fill4<<<1, 16>>>((float4*)gcnt, 0.f, NG / 4);
    k_pool<<<(N + 63) / 64, 128>>>(hbuf, batch, N);
    k_final<<<(NG * CD + 255) / 256, 256>>>(lin_W, lin_b, (float*)d_out);
}

// round 12
// speedup vs baseline: 3.3967x; 1.2419x over previous
#include <cuda_runtime.h>
#include <cuda_bf16.h>
#include <cstdint>

#define NN   50000
#define EE   400000
#define NH   4
#define CD   128
#define HC   512
#define NG   64
#define NT_M 391          // ceil(50000/128) M-tiles
#define TILE_ELEMS 16384  // 128x128 bf16 tile
#define NB_SCAN 196       // ceil(50000/256)

// ---------------- device scratch ----------------
__device__ float g_xl[(size_t)NN * HC];
__device__ float g_xr[(size_t)NN * HC];
__device__ float g_h[(size_t)NN * CD];
__device__ float g_gsum[NG * CD];
__device__ float g_gcnt[NG];
__device__ int   g_is64;
// CSR-by-dst (built once per launch; dst is layer-invariant)
__device__ int g_cnt[NN];
__device__ int g_rowptr[NN + 1];
__device__ int g_bsum[256];
__device__ int g_pos[NN];
__device__ int g_ssrc[EE];
// row-major bf16 hi/lo operands for tensor-core GEMM (zero-init covers tail rows)
__device__ __align__(16) unsigned short g_ahi[(size_t)NT_M * TILE_ELEMS];
__device__ __align__(16) unsigned short g_alo[(size_t)NT_M * TILE_ELEMS];
__device__ __align__(16) unsigned short g_bhi[2 * 128 * 512];   // [side][k][n]
__device__ __align__(16) unsigned short g_blo[2 * 128 * 512];

// ---------------- generic helpers ----------------
__device__ __forceinline__ long long ld_idx(const void* p, long long i, int is64) {
    if (is64) return ((const long long*)p)[i];
    return (long long)((const int*)p)[i];
}

// ---------------- mma.sync building blocks ----------------
__device__ __forceinline__ uint32_t smem_u32(const void* p) {
    uint32_t a;
    asm("{ .reg .u64 t; cvta.to.shared.u64 t, %1; cvt.u32.u64 %0, t; }" : "=r"(a) : "l"(p));
    return a;
}
__device__ __forceinline__ void ldsm_x4(uint32_t* r, uint32_t addr) {
    asm volatile("ldmatrix.sync.aligned.m8n8.x4.shared.b16 {%0,%1,%2,%3}, [%4];"
                 : "=r"(r[0]), "=r"(r[1]), "=r"(r[2]), "=r"(r[3]) : "r"(addr));
}
__device__ __forceinline__ void ldsm_x4_t(uint32_t* r, uint32_t addr) {
    asm volatile("ldmatrix.sync.aligned.m8n8.x4.trans.shared.b16 {%0,%1,%2,%3}, [%4];"
                 : "=r"(r[0]), "=r"(r[1]), "=r"(r[2]), "=r"(r[3]) : "r"(addr));
}
__device__ __forceinline__ void mma_bf16(float* d, const uint32_t* a, const uint32_t* b) {
    asm volatile("mma.sync.aligned.m16n8k16.row.col.f32.bf16.bf16.f32 "
                 "{%0,%1,%2,%3}, {%4,%5,%6,%7}, {%8,%9}, {%0,%1,%2,%3};"
                 : "+f"(d[0]), "+f"(d[1]), "+f"(d[2]), "+f"(d[3])
                 : "r"(a[0]), "r"(a[1]), "r"(a[2]), "r"(a[3]), "r"(b[0]), "r"(b[1]));
}

// ---------------- index dtype detection ----------------
__global__ void k_detect(const unsigned int* __restrict__ w, int npairs) {
    __shared__ int s_any;
    if (threadIdx.x == 0) s_any = 0;
    __syncthreads();
    int any = 0;
    for (int i = threadIdx.x; i < npairs; i += blockDim.x)
        if (w[2 * i + 1] != 0u) any = 1;
    if (any) atomicOr(&s_any, 1);
    __syncthreads();
    if (threadIdx.x == 0) g_is64 = s_any ? 0 : 1;
}

// ---------------- fills ----------------
__global__ void k_fill4(float4* __restrict__ p, float v, int n4) {
    float4 q = make_float4(v, v, v, v);
    for (int i = blockIdx.x * blockDim.x + threadIdx.x; i < n4; i += gridDim.x * blockDim.x)
        p[i] = q;
}
__global__ void k_zero_i(int* __restrict__ p, int n) {
    int i = blockIdx.x * blockDim.x + threadIdx.x;
    if (i < n) p[i] = 0;
}

// ---------------- CSR build: histogram + scan + scatter ----------------
__global__ void k_hist(const void* __restrict__ eidx, int* __restrict__ cnt, int E) {
    int e = blockIdx.x * blockDim.x + threadIdx.x;
    if (e >= E) return;
    int d = (int)ld_idx(eidx, (long long)E + e, g_is64);
    atomicAdd(&cnt[d], 1);
}
__global__ void k_scanA(const int* __restrict__ cnt, int* __restrict__ rowptr,
                        int* __restrict__ bsum, int n) {
    __shared__ int sh[256];
    int i = blockIdx.x * 256 + threadIdx.x;
    int v = (i < n) ? cnt[i] : 0;
    sh[threadIdx.x] = v;
    __syncthreads();
#pragma unroll
    for (int o = 1; o < 256; o <<= 1) {
        int t = (threadIdx.x >= o) ? sh[threadIdx.x - o] : 0;
        __syncthreads();
        sh[threadIdx.x] += t;
        __syncthreads();
    }
    if (i < n) rowptr[i] = sh[threadIdx.x] - v;   // exclusive
    if (threadIdx.x == 255) bsum[blockIdx.x] = sh[255];
}
__global__ void k_scanB(int* __restrict__ bsum, int nb) {
    __shared__ int sh[256];
    int v = (threadIdx.x < nb) ? bsum[threadIdx.x] : 0;
    sh[threadIdx.x] = v;
    __syncthreads();
#pragma unroll
    for (int o = 1; o < 256; o <<= 1) {
        int t = (threadIdx.x >= o) ? sh[threadIdx.x - o] : 0;
        __syncthreads();
        sh[threadIdx.x] += t;
        __syncthreads();
    }
    if (threadIdx.x < nb) bsum[threadIdx.x] = sh[threadIdx.x] - v;  // exclusive
}
__global__ void k_scanC(int* __restrict__ rowptr, const int* __restrict__ bsum,
                        int* __restrict__ pos, int n, int E) {
    int i = blockIdx.x * 256 + threadIdx.x;
    if (i < n) { rowptr[i] += bsum[blockIdx.x]; pos[i] = 0; }
    if (i == n) rowptr[n] = E;
}
__global__ void k_scatter(const void* __restrict__ eidx, const int* __restrict__ rowptr,
                          int* __restrict__ pos, int* __restrict__ ssrc, int E) {
    int e = blockIdx.x * blockDim.x + threadIdx.x;
    if (e >= E) return;
    int is64 = g_is64;
    int s = (int)ld_idx(eidx, e, is64);
    int d = (int)ld_idx(eidx, (long long)E + e, is64);
    int p = rowptr[d] + atomicAdd(&pos[d], 1);
    ssrc[p] = s;
}

// ---------------- layer-0 GEMM (K=3): xl and xr in one pass ----------------
__global__ __launch_bounds__(256) void k_gemm3(
    const float* __restrict__ x,
    const float* __restrict__ Wl, const float* __restrict__ bl,
    const float* __restrict__ Wr, const float* __restrict__ br,
    float* __restrict__ xl, float* __restrict__ xr, int N)
{
    __shared__ float s[1536 * 2 + 512 * 2];
    float* sWl = s;          float* sWr = s + 1536;
    float* sbl = s + 3072;   float* sbr = s + 3584;
    for (int i = threadIdx.x; i < 1536; i += 256) { sWl[i] = Wl[i]; sWr[i] = Wr[i]; }
    for (int i = threadIdx.x; i < 512;  i += 256) { sbl[i] = bl[i]; sbr[i] = br[i]; }
    __syncthreads();
    int total = N * 128;
    for (int t = blockIdx.x * blockDim.x + threadIdx.x; t < total; t += gridDim.x * blockDim.x) {
        int n = t >> 7, jv = (t & 127) << 2;
        float x0 = x[n * 3 + 0], x1 = x[n * 3 + 1], x2 = x[n * 3 + 2];
        {
            float4 w0 = *(float4*)&sWl[jv], w1 = *(float4*)&sWl[512 + jv], w2 = *(float4*)&sWl[1024 + jv];
            float4 b = *(float4*)&sbl[jv];
            float4 o;
            o.x = x0 * w0.x + x1 * w1.x + x2 * w2.x + b.x;
            o.y = x0 * w0.y + x1 * w1.y + x2 * w2.y + b.y;
            o.z = x0 * w0.z + x1 * w1.z + x2 * w2.z + b.z;
            o.w = x0 * w0.w + x1 * w1.w + x2 * w2.w + b.w;
            *(float4*)(xl + (size_t)n * HC + jv) = o;
        }
        {
            float4 w0 = *(float4*)&sWr[jv], w1 = *(float4*)&sWr[512 + jv], w2 = *(float4*)&sWr[1024 + jv];
            float4 b = *(float4*)&sbr[jv];
            float4 o;
            o.x = x0 * w0.x + x1 * w1.x + x2 * w2.x + b.x;
            o.y = x0 * w0.y + x1 * w1.y + x2 * w2.y + b.y;
            o.z = x0 * w0.z + x1 * w1.z + x2 * w2.z + b.z;
            o.w = x0 * w0.w + x1 * w1.w + x2 * w2.w + b.w;
            *(float4*)(xr + (size_t)n * HC + jv) = o;
        }
    }
}

// ---------------- weight prep: W[128,512] -> hi/lo bf16 row-major ----------------
__global__ void k_prep_w(const float* __restrict__ Wl, const float* __restrict__ Wr,
                         unsigned short* __restrict__ bhi, unsigned short* __restrict__ blo)
{
    int t = blockIdx.x * blockDim.x + threadIdx.x;
    if (t >= 16384) return;
    int side = t >> 13;
    int idx8 = (t & 8191) << 3;
    const float* W = side ? Wr : Wl;
    __align__(16) __nv_bfloat16 hi[8], lo[8];
#pragma unroll
    for (int j = 0; j < 8; j++) {
        float v = W[idx8 + j];
        __nv_bfloat16 h = __float2bfloat16(v);
        hi[j] = h;
        lo[j] = __float2bfloat16(v - __bfloat162float(h));
    }
    *(uint4*)(bhi + side * 65536 + idx8) = *(uint4*)hi;
    *(uint4*)(blo + side * 65536 + idx8) = *(uint4*)lo;
}

// ---------------- tensor-core GEMM via mma.sync (verified R11) ----------------
__global__ __launch_bounds__(256) void k_mma(
    const unsigned short* __restrict__ ahi, const unsigned short* __restrict__ alo,
    const unsigned short* __restrict__ bhi_g, const unsigned short* __restrict__ blo_g,
    const float* __restrict__ bl, const float* __restrict__ br,
    float* __restrict__ xl, float* __restrict__ xr, int M)
{
    extern __shared__ __align__(16) char smem[];
    const int mt = blockIdx.y, nt8 = blockIdx.x;
    const int side = nt8 >> 2, ntile = nt8 & 3;
    const int tid = threadIdx.x, wid = tid >> 5, lane = tid & 31;

    {
        const char* gA0 = (const char*)ahi + (size_t)mt * 32768;
        const char* gA1 = (const char*)alo + (size_t)mt * 32768;
        const char* gB0 = (const char*)bhi_g + (size_t)side * 131072;
        const char* gB1 = (const char*)blo_g + (size_t)side * 131072;
#pragma unroll 2
        for (int i = tid; i < 2048; i += 256) {
            int r = i >> 4, g = i & 15;
            int half = g >> 3, gg = g & 7;
            int dst = half * 16384 + r * 128 + ((gg * 16) ^ ((r & 7) << 4));
            *(uint4*)(smem + dst)          = *(const uint4*)(gA0 + r * 256 + g * 16);
            *(uint4*)(smem + 32768 + dst)  = *(const uint4*)(gA1 + r * 256 + g * 16);
            *(uint4*)(smem + 65536 + dst)  = *(const uint4*)(gB0 + r * 1024 + ntile * 256 + g * 16);
            *(uint4*)(smem + 98304 + dst)  = *(const uint4*)(gB1 + r * 1024 + ntile * 256 + g * 16);
        }
    }
    __syncthreads();

    const uint32_t sbase = smem_u32(smem);
    const int m0 = (wid >> 1) * 32, n0 = (wid & 1) * 64;

    float acc[2][8][4];
#pragma unroll
    for (int i = 0; i < 2; i++)
#pragma unroll
        for (int j = 0; j < 8; j++)
#pragma unroll
            for (int q = 0; q < 4; q++) acc[i][j][q] = 0.f;

#pragma unroll
    for (int ks = 0; ks < 8; ks++) {
        uint32_t aH[2][4], aL[2][4];
        {
            int cb = ((ks & 3) << 5) + ((lane >> 4) << 4);
#pragma unroll
            for (int mt2 = 0; mt2 < 2; mt2++) {
                int rr = m0 + mt2 * 16 + (lane & 15);
                uint32_t ad = sbase + (ks >> 2) * 16384 + rr * 128 + (cb ^ ((rr & 7) << 4));
                ldsm_x4(aH[mt2], ad);
                ldsm_x4(aL[mt2], ad + 32768);
            }
        }
        int rowk = ks * 16 + (lane & 15);
        int swk = (rowk & 7) << 4;
#pragma unroll
        for (int nc = 0; nc < 4; nc++) {
            int nb = n0 + nc * 16;
            uint32_t cbyte = ((nb & 63) << 1) + ((lane >> 4) << 4);
            uint32_t ad = sbase + 65536 + (nb >> 6) * 16384 + rowk * 128 + (cbyte ^ swk);
            uint32_t bH[4], bL[4];
            ldsm_x4_t(bH, ad);
            ldsm_x4_t(bL, ad + 32768);
#pragma unroll
            for (int mt2 = 0; mt2 < 2; mt2++) {
#pragma unroll
                for (int j = 0; j < 2; j++) {
                    float* d = acc[mt2][nc * 2 + j];
                    mma_bf16(d, aH[mt2], bH + 2 * j);
                    mma_bf16(d, aH[mt2], bL + 2 * j);
                    mma_bf16(d, aL[mt2], bH + 2 * j);
                }
            }
        }
    }

    const float* bias = side ? br : bl;
    float* out = side ? xr : xl;
    const int rbase = mt * 128 + m0;
#pragma unroll
    for (int mt2 = 0; mt2 < 2; mt2++) {
        int r0 = rbase + mt2 * 16 + (lane >> 2);
#pragma unroll
        for (int nt = 0; nt < 8; nt++) {
            int c = ntile * 128 + n0 + nt * 8 + (lane & 3) * 2;
            float2 b2 = *(const float2*)(bias + c);
            if (r0 < M) {
                float2 v = make_float2(acc[mt2][nt][0] + b2.x, acc[mt2][nt][1] + b2.y);
                *(float2*)(out + (size_t)r0 * 512 + c) = v;
            }
            if (r0 + 8 < M) {
                float2 v = make_float2(acc[mt2][nt][2] + b2.x, acc[mt2][nt][3] + b2.y);
                *(float2*)(out + (size_t)(r0 + 8) * 512 + c) = v;
            }
        }
    }
}

// ---------------- fused edge kernel: one warp per dst, online softmax ----------------
// out[d,c] = mean_h ( sum_e alpha_eh * xl[src_e, h, c] ); alpha = softmax over dst's edges.
// Single xl gather per edge; flash-style running (max, denom, acc) per head.
// Fused epilogue: head mean + bias + elu -> hout, plus bf16 hi/lo for next GEMM.
__global__ __launch_bounds__(256) void k_edge(
    const int* __restrict__ rowptr, const int* __restrict__ ssrc,
    const float* __restrict__ xl, const float* __restrict__ xr,
    const float* __restrict__ att, const float* __restrict__ bias,
    float* __restrict__ hout,
    unsigned short* __restrict__ ahi, unsigned short* __restrict__ alo, int N)
{
    int w = (blockIdx.x * blockDim.x + threadIdx.x) >> 5;
    int lane = threadIdx.x & 31;
    if (w >= N) return;
    int rs = rowptr[w], re = rowptr[w + 1];

    const float4* xrd = (const float4*)(xr + (size_t)w * HC);
    float4 r0 = xrd[lane], r1 = xrd[32 + lane], r2 = xrd[64 + lane], r3 = xrd[96 + lane];
    const float4* at4 = (const float4*)att;
    float4 w0 = at4[lane], w1 = at4[32 + lane], w2 = at4[64 + lane], w3 = at4[96 + lane];

    float m0 = -1e30f, m1 = -1e30f, m2 = -1e30f, m3 = -1e30f;
    float dn0 = 0.f, dn1 = 0.f, dn2 = 0.f, dn3 = 0.f;
    float4 ac0 = make_float4(0, 0, 0, 0), ac1 = ac0, ac2 = ac0, ac3 = ac0;

    for (int j = rs; j < re; j++) {
        int s = ssrc[j];
        const float4* xls = (const float4*)(xl + (size_t)s * HC);
        float4 a0 = xls[lane], a1 = xls[32 + lane], a2 = xls[64 + lane], a3 = xls[96 + lane];

#define LR(u) ((u) > 0.f ? (u) : 0.2f * (u))
#define DOTLR(a, r, wv) (LR(a.x + r.x) * wv.x + LR(a.y + r.y) * wv.y + \
                         LR(a.z + r.z) * wv.z + LR(a.w + r.w) * wv.w)
        float p0 = DOTLR(a0, r0, w0);
        float p1 = DOTLR(a1, r1, w1);
        float p2 = DOTLR(a2, r2, w2);
        float p3 = DOTLR(a3, r3, w3);
#undef DOTLR
#undef LR
#pragma unroll
        for (int o = 16; o > 0; o >>= 1) {
            p0 += __shfl_xor_sync(0xffffffffu, p0, o);
            p1 += __shfl_xor_sync(0xffffffffu, p1, o);
            p2 += __shfl_xor_sync(0xffffffffu, p2, o);
            p3 += __shfl_xor_sync(0xffffffffu, p3, o);
        }
        // online softmax update per head
        {
            float mn = fmaxf(m0, p0), sc = __expf(m0 - mn), pe = __expf(p0 - mn);
            dn0 = dn0 * sc + pe; m0 = mn;
            ac0.x = ac0.x * sc + pe * a0.x; ac0.y = ac0.y * sc + pe * a0.y;
            ac0.z = ac0.z * sc + pe * a0.z; ac0.w = ac0.w * sc + pe * a0.w;
        }
        {
            float mn = fmaxf(m1, p1), sc = __expf(m1 - mn), pe = __expf(p1 - mn);
            dn1 = dn1 * sc + pe; m1 = mn;
            ac1.x = ac1.x * sc + pe * a1.x; ac1.y = ac1.y * sc + pe * a1.y;
            ac1.z = ac1.z * sc + pe * a1.z; ac1.w = ac1.w * sc + pe * a1.w;
        }
        {
            float mn = fmaxf(m2, p2), sc = __expf(m2 - mn), pe = __expf(p2 - mn);
            dn2 = dn2 * sc + pe; m2 = mn;
            ac2.x = ac2.x * sc + pe * a2.x; ac2.y = ac2.y * sc + pe * a2.y;
            ac2.z = ac2.z * sc + pe * a2.z; ac2.w = ac2.w * sc + pe * a2.w;
        }
        {
            float mn = fmaxf(m3, p3), sc = __expf(m3 - mn), pe = __expf(p3 - mn);
            dn3 = dn3 * sc + pe; m3 = mn;
            ac3.x = ac3.x * sc + pe * a3.x; ac3.y = ac3.y * sc + pe * a3.y;
            ac3.z = ac3.z * sc + pe * a3.z; ac3.w = ac3.w * sc + pe * a3.w;
        }
    }

    float i0 = dn0 > 0.f ? 0.25f / dn0 : 0.f;
    float i1 = dn1 > 0.f ? 0.25f / dn1 : 0.f;
    float i2 = dn2 > 0.f ? 0.25f / dn2 : 0.f;
    float i3 = dn3 > 0.f ? 0.25f / dn3 : 0.f;

    int c0 = lane * 4;
    float4 b4 = *(const float4*)(bias + c0);
    float v[4];
    v[0] = ac0.x * i0 + ac1.x * i1 + ac2.x * i2 + ac3.x * i3 + b4.x;
    v[1] = ac0.y * i0 + ac1.y * i1 + ac2.y * i2 + ac3.y * i3 + b4.y;
    v[2] = ac0.z * i0 + ac1.z * i1 + ac2.z * i2 + ac3.z * i3 + b4.z;
    v[3] = ac0.w * i0 + ac1.w * i1 + ac2.w * i2 + ac3.w * i3 + b4.w;

    __align__(8) __nv_bfloat16 hi[4], lo[4];
#pragma unroll
    for (int j = 0; j < 4; j++) {
        float e = v[j] > 0.f ? v[j] : (expf(v[j]) - 1.f);
        v[j] = e;
        __nv_bfloat16 h = __float2bfloat16(e);
        hi[j] = h;
        lo[j] = __float2bfloat16(e - __bfloat162float(h));
    }
    *(float4*)(hout + (size_t)w * CD + c0) = make_float4(v[0], v[1], v[2], v[3]);
    *(uint2*)(ahi + (size_t)w * CD + c0) = *(uint2*)hi;
    *(uint2*)(alo + (size_t)w * CD + c0) = *(uint2*)lo;
}

// ---------------- global mean pool (batch sorted) ----------------
__global__ void k_pool(const float* __restrict__ h, const void* __restrict__ batch, int N)
{
    int c = threadIdx.x;
    int n0 = blockIdx.x * 64;
    int n1 = n0 + 64; if (n1 > N) n1 = N;
    int is64 = g_is64;
    long long cur = -1; float acc = 0.f, cnt = 0.f;
    for (int n = n0; n < n1; n++) {
        long long g = ld_idx(batch, n, is64);
        if (g != cur) {
            if (cur >= 0) {
                atomicAdd(&g_gsum[(int)cur * CD + c], acc);
                if (c == 0) atomicAdd(&g_gcnt[(int)cur], cnt);
            }
            cur = g; acc = 0.f; cnt = 0.f;
        }
        acc += h[(size_t)n * CD + c];
        cnt += 1.f;
    }
    if (cur >= 0) {
        atomicAdd(&g_gsum[(int)cur * CD + c], acc);
        if (c == 0) atomicAdd(&g_gcnt[(int)cur], cnt);
    }
}

// ---------------- final linear ----------------
__global__ void k_final(const float* __restrict__ W, const float* __restrict__ b,
                        float* __restrict__ out)
{
    int t = blockIdx.x * blockDim.x + threadIdx.x;
    if (t >= NG * CD) return;
    int g = t >> 7, z = t & 127;
    float inv = 1.f / fmaxf(g_gcnt[g], 1.f);
    float acc = 0.f;
#pragma unroll 8
    for (int c = 0; c < CD; c++)
        acc += g_gsum[g * CD + c] * W[c * CD + z];
    out[t] = acc * inv + b[z];
}

// ---------------- host orchestration ----------------
extern "C" void kernel_launch(void* const* d_in, const int* in_sizes, int n_in,
                              void* d_out, int out_size)
{
    const float* x     = (const float*)d_in[0];
    const void*  eidx  = d_in[1];
    const void*  batch = d_in[2];
    const float* lin_W = (const float*)d_in[21];
    const float* lin_b = (const float*)d_in[22];

    const int N = in_sizes[2];
    const int E = in_sizes[1] / 2;

    float *xl, *xr, *hbuf, *gsum, *gcnt;
    int *cnt, *rowptr, *bsum, *pos, *ssrc;
    unsigned short *ahi, *alo, *bhi, *blo;
    cudaGetSymbolAddress((void**)&xl,     g_xl);
    cudaGetSymbolAddress((void**)&xr,     g_xr);
    cudaGetSymbolAddress((void**)&hbuf,   g_h);
    cudaGetSymbolAddress((void**)&gsum,   g_gsum);
    cudaGetSymbolAddress((void**)&gcnt,   g_gcnt);
    cudaGetSymbolAddress((void**)&cnt,    g_cnt);
    cudaGetSymbolAddress((void**)&rowptr, g_rowptr);
    cudaGetSymbolAddress((void**)&bsum,   g_bsum);
    cudaGetSymbolAddress((void**)&pos,    g_pos);
    cudaGetSymbolAddress((void**)&ssrc,   g_ssrc);
    cudaGetSymbolAddress((void**)&ahi,    g_ahi);
    cudaGetSymbolAddress((void**)&alo,    g_alo);
    cudaGetSymbolAddress((void**)&bhi,    g_bhi);
    cudaGetSymbolAddress((void**)&blo,    g_blo);

    const int MMA_SMEM = 131072;
    cudaFuncSetAttribute(k_mma, cudaFuncAttributeMaxDynamicSharedMemorySize, MMA_SMEM);

    // ---- one-time: index dtype + CSR-by-dst build ----
    k_detect<<<1, 256>>>((const unsigned int*)eidx, 4096);
    k_zero_i<<<(N + 255) / 256, 256>>>(cnt, N);
    k_hist<<<(E + 255) / 256, 256>>>(eidx, cnt, E);
    k_scanA<<<NB_SCAN, 256>>>(cnt, rowptr, bsum, N);
    k_scanB<<<1, 256>>>(bsum, NB_SCAN);
    k_scanC<<<(N + 256) / 256, 256>>>(rowptr, bsum, pos, N, E);
    k_scatter<<<(E + 255) / 256, 256>>>(eidx, rowptr, pos, ssrc, E);

    for (int l = 0; l < 3; l++) {
        const float* Wl  = (const float*)d_in[3 + 6 * l + 0];
        const float* bl  = (const float*)d_in[3 + 6 * l + 1];
        const float* Wr  = (const float*)d_in[3 + 6 * l + 2];
        const float* br  = (const float*)d_in[3 + 6 * l + 3];
        const float* att = (const float*)d_in[3 + 6 * l + 4];
        const float* bb  = (const float*)d_in[3 + 6 * l + 5];

        if (l == 0) {
            k_gemm3<<<2048, 256>>>(x, Wl, bl, Wr, br, xl, xr, N);
        } else {
            k_prep_w<<<64, 256>>>(Wl, Wr, bhi, blo);
            dim3 gg(8, NT_M);
            k_mma<<<gg, 256, MMA_SMEM>>>(ahi, alo, bhi, blo, bl, br, xl, xr, N);
        }

        // fused scores + softmax + aggregation + epilogue (one warp per dst)
        k_edge<<<(N * 32 + 255) / 256, 256>>>(rowptr, ssrc, xl, xr, att, bb,
                                              hbuf, ahi, alo, N);
    }

    k_fill4<<<8, 256>>>((float4*)gsum, 0.f, NG * CD / 4);
    k_fill4<<<1, 16>>>((float4*)gcnt, 0.f, NG / 4);
    k_pool<<<(N + 63) / 64, 128>>>(hbuf, batch, N);
    k_final<<<(NG * CD + 255) / 256, 256>>>(lin_W, lin_b, (float*)d_out);
}

// round 13
// speedup vs baseline: 3.5573x; 1.0473x over previous
#include <cuda_runtime.h>
#include <cuda_bf16.h>
#include <cstdint>

#define NN   50000
#define EE   400000
#define NH   4
#define CD   128
#define HC   512
#define NG   64
#define NT_M 391          // ceil(50000/128) M-tiles
#define TILE_ELEMS 16384  // 128x128 bf16 tile
#define NB_SCAN 196       // ceil(50000/256)

// ---------------- device scratch ----------------
__device__ float g_xl[(size_t)NN * HC];
__device__ float g_xr[(size_t)NN * HC];
__device__ float g_h[(size_t)NN * CD];
__device__ float g_gsum[NG * CD];
__device__ float g_gcnt[NG];
__device__ int   g_is64;
// CSR-by-dst (built once per launch; dst is layer-invariant)
__device__ int g_cnt[NN];
__device__ int g_rowptr[NN + 1];
__device__ int g_bsum[256];
__device__ int g_pos[NN];
__device__ int g_ssrc[EE];
// row-major bf16 hi/lo operands for tensor-core GEMM (zero-init covers tail rows)
__device__ __align__(16) unsigned short g_ahi[(size_t)NT_M * TILE_ELEMS];
__device__ __align__(16) unsigned short g_alo[(size_t)NT_M * TILE_ELEMS];
__device__ __align__(16) unsigned short g_bhi[2 * 128 * 512];   // [side][k][n]
__device__ __align__(16) unsigned short g_blo[2 * 128 * 512];

// ---------------- generic helpers ----------------
__device__ __forceinline__ long long ld_idx(const void* p, long long i, int is64) {
    if (is64) return ((const long long*)p)[i];
    return (long long)((const int*)p)[i];
}

// ---------------- mma.sync building blocks ----------------
__device__ __forceinline__ uint32_t smem_u32(const void* p) {
    uint32_t a;
    asm("{ .reg .u64 t; cvta.to.shared.u64 t, %1; cvt.u32.u64 %0, t; }" : "=r"(a) : "l"(p));
    return a;
}
__device__ __forceinline__ void ldsm_x4(uint32_t* r, uint32_t addr) {
    asm volatile("ldmatrix.sync.aligned.m8n8.x4.shared.b16 {%0,%1,%2,%3}, [%4];"
                 : "=r"(r[0]), "=r"(r[1]), "=r"(r[2]), "=r"(r[3]) : "r"(addr));
}
__device__ __forceinline__ void ldsm_x4_t(uint32_t* r, uint32_t addr) {
    asm volatile("ldmatrix.sync.aligned.m8n8.x4.trans.shared.b16 {%0,%1,%2,%3}, [%4];"
                 : "=r"(r[0]), "=r"(r[1]), "=r"(r[2]), "=r"(r[3]) : "r"(addr));
}
__device__ __forceinline__ void mma_bf16(float* d, const uint32_t* a, const uint32_t* b) {
    asm volatile("mma.sync.aligned.m16n8k16.row.col.f32.bf16.bf16.f32 "
                 "{%0,%1,%2,%3}, {%4,%5,%6,%7}, {%8,%9}, {%0,%1,%2,%3};"
                 : "+f"(d[0]), "+f"(d[1]), "+f"(d[2]), "+f"(d[3])
                 : "r"(a[0]), "r"(a[1]), "r"(a[2]), "r"(a[3]), "r"(b[0]), "r"(b[1]));
}

// ---------------- index dtype detection ----------------
__global__ void k_detect(const unsigned int* __restrict__ w, int npairs) {
    __shared__ int s_any;
    if (threadIdx.x == 0) s_any = 0;
    __syncthreads();
    int any = 0;
    for (int i = threadIdx.x; i < npairs; i += blockDim.x)
        if (w[2 * i + 1] != 0u) any = 1;
    if (any) atomicOr(&s_any, 1);
    __syncthreads();
    if (threadIdx.x == 0) g_is64 = s_any ? 0 : 1;
}

// ---------------- fills ----------------
__global__ void k_fill4(float4* __restrict__ p, float v, int n4) {
    float4 q = make_float4(v, v, v, v);
    for (int i = blockIdx.x * blockDim.x + threadIdx.x; i < n4; i += gridDim.x * blockDim.x)
        p[i] = q;
}
__global__ void k_zero_i(int* __restrict__ p, int n) {
    int i = blockIdx.x * blockDim.x + threadIdx.x;
    if (i < n) p[i] = 0;
}

// ---------------- CSR build: histogram + scan + scatter ----------------
__global__ void k_hist(const void* __restrict__ eidx, int* __restrict__ cnt, int E) {
    int e = blockIdx.x * blockDim.x + threadIdx.x;
    if (e >= E) return;
    int d = (int)ld_idx(eidx, (long long)E + e, g_is64);
    atomicAdd(&cnt[d], 1);
}
__global__ void k_scanA(const int* __restrict__ cnt, int* __restrict__ rowptr,
                        int* __restrict__ bsum, int n) {
    __shared__ int sh[256];
    int i = blockIdx.x * 256 + threadIdx.x;
    int v = (i < n) ? cnt[i] : 0;
    sh[threadIdx.x] = v;
    __syncthreads();
#pragma unroll
    for (int o = 1; o < 256; o <<= 1) {
        int t = (threadIdx.x >= o) ? sh[threadIdx.x - o] : 0;
        __syncthreads();
        sh[threadIdx.x] += t;
        __syncthreads();
    }
    if (i < n) rowptr[i] = sh[threadIdx.x] - v;   // exclusive
    if (threadIdx.x == 255) bsum[blockIdx.x] = sh[255];
}
__global__ void k_scanB(int* __restrict__ bsum, int nb) {
    __shared__ int sh[256];
    int v = (threadIdx.x < nb) ? bsum[threadIdx.x] : 0;
    sh[threadIdx.x] = v;
    __syncthreads();
#pragma unroll
    for (int o = 1; o < 256; o <<= 1) {
        int t = (threadIdx.x >= o) ? sh[threadIdx.x - o] : 0;
        __syncthreads();
        sh[threadIdx.x] += t;
        __syncthreads();
    }
    if (threadIdx.x < nb) bsum[threadIdx.x] = sh[threadIdx.x] - v;  // exclusive
}
__global__ void k_scanC(int* __restrict__ rowptr, const int* __restrict__ bsum,
                        int* __restrict__ pos, int n, int E) {
    int i = blockIdx.x * 256 + threadIdx.x;
    if (i < n) { rowptr[i] += bsum[blockIdx.x]; pos[i] = 0; }
    if (i == n) rowptr[n] = E;
}
__global__ void k_scatter(const void* __restrict__ eidx, const int* __restrict__ rowptr,
                          int* __restrict__ pos, int* __restrict__ ssrc, int E) {
    int e = blockIdx.x * blockDim.x + threadIdx.x;
    if (e >= E) return;
    int is64 = g_is64;
    int s = (int)ld_idx(eidx, e, is64);
    int d = (int)ld_idx(eidx, (long long)E + e, is64);
    int p = rowptr[d] + atomicAdd(&pos[d], 1);
    ssrc[p] = s;
}

// ---------------- layer-0 GEMM (K=3): xl and xr in one pass ----------------
__global__ __launch_bounds__(256) void k_gemm3(
    const float* __restrict__ x,
    const float* __restrict__ Wl, const float* __restrict__ bl,
    const float* __restrict__ Wr, const float* __restrict__ br,
    float* __restrict__ xl, float* __restrict__ xr, int N)
{
    __shared__ float s[1536 * 2 + 512 * 2];
    float* sWl = s;          float* sWr = s + 1536;
    float* sbl = s + 3072;   float* sbr = s + 3584;
    for (int i = threadIdx.x; i < 1536; i += 256) { sWl[i] = Wl[i]; sWr[i] = Wr[i]; }
    for (int i = threadIdx.x; i < 512;  i += 256) { sbl[i] = bl[i]; sbr[i] = br[i]; }
    __syncthreads();
    int total = N * 128;
    for (int t = blockIdx.x * blockDim.x + threadIdx.x; t < total; t += gridDim.x * blockDim.x) {
        int n = t >> 7, jv = (t & 127) << 2;
        float x0 = x[n * 3 + 0], x1 = x[n * 3 + 1], x2 = x[n * 3 + 2];
        {
            float4 w0 = *(float4*)&sWl[jv], w1 = *(float4*)&sWl[512 + jv], w2 = *(float4*)&sWl[1024 + jv];
            float4 b = *(float4*)&sbl[jv];
            float4 o;
            o.x = x0 * w0.x + x1 * w1.x + x2 * w2.x + b.x;
            o.y = x0 * w0.y + x1 * w1.y + x2 * w2.y + b.y;
            o.z = x0 * w0.z + x1 * w1.z + x2 * w2.z + b.z;
            o.w = x0 * w0.w + x1 * w1.w + x2 * w2.w + b.w;
            *(float4*)(xl + (size_t)n * HC + jv) = o;
        }
        {
            float4 w0 = *(float4*)&sWr[jv], w1 = *(float4*)&sWr[512 + jv], w2 = *(float4*)&sWr[1024 + jv];
            float4 b = *(float4*)&sbr[jv];
            float4 o;
            o.x = x0 * w0.x + x1 * w1.x + x2 * w2.x + b.x;
            o.y = x0 * w0.y + x1 * w1.y + x2 * w2.y + b.y;
            o.z = x0 * w0.z + x1 * w1.z + x2 * w2.z + b.z;
            o.w = x0 * w0.w + x1 * w1.w + x2 * w2.w + b.w;
            *(float4*)(xr + (size_t)n * HC + jv) = o;
        }
    }
}

// ---------------- weight prep: W[128,512] -> hi/lo bf16 row-major ----------------
__global__ void k_prep_w(const float* __restrict__ Wl, const float* __restrict__ Wr,
                         unsigned short* __restrict__ bhi, unsigned short* __restrict__ blo)
{
    int t = blockIdx.x * blockDim.x + threadIdx.x;
    if (t >= 16384) return;
    int side = t >> 13;
    int idx8 = (t & 8191) << 3;
    const float* W = side ? Wr : Wl;
    __align__(16) __nv_bfloat16 hi[8], lo[8];
#pragma unroll
    for (int j = 0; j < 8; j++) {
        float v = W[idx8 + j];
        __nv_bfloat16 h = __float2bfloat16(v);
        hi[j] = h;
        lo[j] = __float2bfloat16(v - __bfloat162float(h));
    }
    *(uint4*)(bhi + side * 65536 + idx8) = *(uint4*)hi;
    *(uint4*)(blo + side * 65536 + idx8) = *(uint4*)lo;
}

// ---------------- tensor-core GEMM via mma.sync (verified R11/R12) ----------------
__global__ __launch_bounds__(256) void k_mma(
    const unsigned short* __restrict__ ahi, const unsigned short* __restrict__ alo,
    const unsigned short* __restrict__ bhi_g, const unsigned short* __restrict__ blo_g,
    const float* __restrict__ bl, const float* __restrict__ br,
    float* __restrict__ xl, float* __restrict__ xr, int M)
{
    extern __shared__ __align__(16) char smem[];
    const int mt = blockIdx.y, nt8 = blockIdx.x;
    const int side = nt8 >> 2, ntile = nt8 & 3;
    const int tid = threadIdx.x, wid = tid >> 5, lane = tid & 31;

    {
        const char* gA0 = (const char*)ahi + (size_t)mt * 32768;
        const char* gA1 = (const char*)alo + (size_t)mt * 32768;
        const char* gB0 = (const char*)bhi_g + (size_t)side * 131072;
        const char* gB1 = (const char*)blo_g + (size_t)side * 131072;
#pragma unroll 2
        for (int i = tid; i < 2048; i += 256) {
            int r = i >> 4, g = i & 15;
            int half = g >> 3, gg = g & 7;
            int dst = half * 16384 + r * 128 + ((gg * 16) ^ ((r & 7) << 4));
            *(uint4*)(smem + dst)          = *(const uint4*)(gA0 + r * 256 + g * 16);
            *(uint4*)(smem + 32768 + dst)  = *(const uint4*)(gA1 + r * 256 + g * 16);
            *(uint4*)(smem + 65536 + dst)  = *(const uint4*)(gB0 + r * 1024 + ntile * 256 + g * 16);
            *(uint4*)(smem + 98304 + dst)  = *(const uint4*)(gB1 + r * 1024 + ntile * 256 + g * 16);
        }
    }
    __syncthreads();

    const uint32_t sbase = smem_u32(smem);
    const int m0 = (wid >> 1) * 32, n0 = (wid & 1) * 64;

    float acc[2][8][4];
#pragma unroll
    for (int i = 0; i < 2; i++)
#pragma unroll
        for (int j = 0; j < 8; j++)
#pragma unroll
            for (int q = 0; q < 4; q++) acc[i][j][q] = 0.f;

#pragma unroll
    for (int ks = 0; ks < 8; ks++) {
        uint32_t aH[2][4], aL[2][4];
        {
            int cb = ((ks & 3) << 5) + ((lane >> 4) << 4);
#pragma unroll
            for (int mt2 = 0; mt2 < 2; mt2++) {
                int rr = m0 + mt2 * 16 + (lane & 15);
                uint32_t ad = sbase + (ks >> 2) * 16384 + rr * 128 + (cb ^ ((rr & 7) << 4));
                ldsm_x4(aH[mt2], ad);
                ldsm_x4(aL[mt2], ad + 32768);
            }
        }
        int rowk = ks * 16 + (lane & 15);
        int swk = (rowk & 7) << 4;
#pragma unroll
        for (int nc = 0; nc < 4; nc++) {
            int nb = n0 + nc * 16;
            uint32_t cbyte = ((nb & 63) << 1) + ((lane >> 4) << 4);
            uint32_t ad = sbase + 65536 + (nb >> 6) * 16384 + rowk * 128 + (cbyte ^ swk);
            uint32_t bH[4], bL[4];
            ldsm_x4_t(bH, ad);
            ldsm_x4_t(bL, ad + 32768);
#pragma unroll
            for (int mt2 = 0; mt2 < 2; mt2++) {
#pragma unroll
                for (int j = 0; j < 2; j++) {
                    float* d = acc[mt2][nc * 2 + j];
                    mma_bf16(d, aH[mt2], bH + 2 * j);
                    mma_bf16(d, aH[mt2], bL + 2 * j);
                    mma_bf16(d, aL[mt2], bH + 2 * j);
                }
            }
        }
    }

    const float* bias = side ? br : bl;
    float* out = side ? xr : xl;
    const int rbase = mt * 128 + m0;
#pragma unroll
    for (int mt2 = 0; mt2 < 2; mt2++) {
        int r0 = rbase + mt2 * 16 + (lane >> 2);
#pragma unroll
        for (int nt = 0; nt < 8; nt++) {
            int c = ntile * 128 + n0 + nt * 8 + (lane & 3) * 2;
            float2 b2 = *(const float2*)(bias + c);
            if (r0 < M) {
                float2 v = make_float2(acc[mt2][nt][0] + b2.x, acc[mt2][nt][1] + b2.y);
                *(float2*)(out + (size_t)r0 * 512 + c) = v;
            }
            if (r0 + 8 < M) {
                float2 v = make_float2(acc[mt2][nt][2] + b2.x, acc[mt2][nt][3] + b2.y);
                *(float2*)(out + (size_t)(r0 + 8) * 512 + c) = v;
            }
        }
    }
}

// ---------------- fused edge kernel: one warp per dst, online softmax ----------------
// Streaming hints: xr rows and all outputs are single-use -> __ldcs/__stcs (evict-first),
// preserving L2 residency for the randomly-gathered xl (102.4 MB, ~8 reuses/row).
// wh: write hout (only needed for last layer); wab: write ahi/alo (only layers 0,1).
__global__ __launch_bounds__(256) void k_edge(
    const int* __restrict__ rowptr, const int* __restrict__ ssrc,
    const float* __restrict__ xl, const float* __restrict__ xr,
    const float* __restrict__ att, const float* __restrict__ bias,
    float* __restrict__ hout,
    unsigned short* __restrict__ ahi, unsigned short* __restrict__ alo,
    int N, int wh, int wab)
{
    int w = (blockIdx.x * blockDim.x + threadIdx.x) >> 5;
    int lane = threadIdx.x & 31;
    if (w >= N) return;
    int rs = rowptr[w], re = rowptr[w + 1];

    const float4* xrd = (const float4*)(xr + (size_t)w * HC);
    float4 r0 = __ldcs(xrd + lane), r1 = __ldcs(xrd + 32 + lane);
    float4 r2 = __ldcs(xrd + 64 + lane), r3 = __ldcs(xrd + 96 + lane);
    const float4* at4 = (const float4*)att;
    float4 w0 = at4[lane], w1 = at4[32 + lane], w2 = at4[64 + lane], w3 = at4[96 + lane];

    float m0 = -1e30f, m1 = -1e30f, m2 = -1e30f, m3 = -1e30f;
    float dn0 = 0.f, dn1 = 0.f, dn2 = 0.f, dn3 = 0.f;
    float4 ac0 = make_float4(0, 0, 0, 0), ac1 = ac0, ac2 = ac0, ac3 = ac0;

    for (int j = rs; j < re; j++) {
        int s = ssrc[j];
        const float4* xls = (const float4*)(xl + (size_t)s * HC);
        float4 a0 = xls[lane], a1 = xls[32 + lane], a2 = xls[64 + lane], a3 = xls[96 + lane];

#define LR(u) ((u) > 0.f ? (u) : 0.2f * (u))
#define DOTLR(a, r, wv) (LR(a.x + r.x) * wv.x + LR(a.y + r.y) * wv.y + \
                         LR(a.z + r.z) * wv.z + LR(a.w + r.w) * wv.w)
        float p0 = DOTLR(a0, r0, w0);
        float p1 = DOTLR(a1, r1, w1);
        float p2 = DOTLR(a2, r2, w2);
        float p3 = DOTLR(a3, r3, w3);
#undef DOTLR
#undef LR
#pragma unroll
        for (int o = 16; o > 0; o >>= 1) {
            p0 += __shfl_xor_sync(0xffffffffu, p0, o);
            p1 += __shfl_xor_sync(0xffffffffu, p1, o);
            p2 += __shfl_xor_sync(0xffffffffu, p2, o);
            p3 += __shfl_xor_sync(0xffffffffu, p3, o);
        }
        // online softmax update per head
        {
            float mn = fmaxf(m0, p0), sc = __expf(m0 - mn), pe = __expf(p0 - mn);
            dn0 = dn0 * sc + pe; m0 = mn;
            ac0.x = ac0.x * sc + pe * a0.x; ac0.y = ac0.y * sc + pe * a0.y;
            ac0.z = ac0.z * sc + pe * a0.z; ac0.w = ac0.w * sc + pe * a0.w;
        }
        {
            float mn = fmaxf(m1, p1), sc = __expf(m1 - mn), pe = __expf(p1 - mn);
            dn1 = dn1 * sc + pe; m1 = mn;
            ac1.x = ac1.x * sc + pe * a1.x; ac1.y = ac1.y * sc + pe * a1.y;
            ac1.z = ac1.z * sc + pe * a1.z; ac1.w = ac1.w * sc + pe * a1.w;
        }
        {
            float mn = fmaxf(m2, p2), sc = __expf(m2 - mn), pe = __expf(p2 - mn);
            dn2 = dn2 * sc + pe; m2 = mn;
            ac2.x = ac2.x * sc + pe * a2.x; ac2.y = ac2.y * sc + pe * a2.y;
            ac2.z = ac2.z * sc + pe * a2.z; ac2.w = ac2.w * sc + pe * a2.w;
        }
        {
            float mn = fmaxf(m3, p3), sc = __expf(m3 - mn), pe = __expf(p3 - mn);
            dn3 = dn3 * sc + pe; m3 = mn;
            ac3.x = ac3.x * sc + pe * a3.x; ac3.y = ac3.y * sc + pe * a3.y;
            ac3.z = ac3.z * sc + pe * a3.z; ac3.w = ac3.w * sc + pe * a3.w;
        }
    }

    float i0 = dn0 > 0.f ? 0.25f / dn0 : 0.f;
    float i1 = dn1 > 0.f ? 0.25f / dn1 : 0.f;
    float i2 = dn2 > 0.f ? 0.25f / dn2 : 0.f;
    float i3 = dn3 > 0.f ? 0.25f / dn3 : 0.f;

    int c0 = lane * 4;
    float4 b4 = *(const float4*)(bias + c0);
    float v[4];
    v[0] = ac0.x * i0 + ac1.x * i1 + ac2.x * i2 + ac3.x * i3 + b4.x;
    v[1] = ac0.y * i0 + ac1.y * i1 + ac2.y * i2 + ac3.y * i3 + b4.y;
    v[2] = ac0.z * i0 + ac1.z * i1 + ac2.z * i2 + ac3.z * i3 + b4.z;
    v[3] = ac0.w * i0 + ac1.w * i1 + ac2.w * i2 + ac3.w * i3 + b4.w;

    __align__(8) __nv_bfloat16 hi[4], lo[4];
#pragma unroll
    for (int j = 0; j < 4; j++) {
        float e = v[j] > 0.f ? v[j] : (expf(v[j]) - 1.f);
        v[j] = e;
        __nv_bfloat16 h = __float2bfloat16(e);
        hi[j] = h;
        lo[j] = __float2bfloat16(e - __bfloat162float(h));
    }
    if (wh)
        __stcs((float4*)(hout + (size_t)w * CD + c0), make_float4(v[0], v[1], v[2], v[3]));
    if (wab) {
        __stcs((uint2*)(ahi + (size_t)w * CD + c0), *(uint2*)hi);
        __stcs((uint2*)(alo + (size_t)w * CD + c0), *(uint2*)lo);
    }
}

// ---------------- global mean pool (batch sorted) ----------------
__global__ void k_pool(const float* __restrict__ h, const void* __restrict__ batch, int N)
{
    int c = threadIdx.x;
    int n0 = blockIdx.x * 64;
    int n1 = n0 + 64; if (n1 > N) n1 = N;
    int is64 = g_is64;
    long long cur = -1; float acc = 0.f, cnt = 0.f;
    for (int n = n0; n < n1; n++) {
        long long g = ld_idx(batch, n, is64);
        if (g != cur) {
            if (cur >= 0) {
                atomicAdd(&g_gsum[(int)cur * CD + c], acc);
                if (c == 0) atomicAdd(&g_gcnt[(int)cur], cnt);
            }
            cur = g; acc = 0.f; cnt = 0.f;
        }
        acc += h[(size_t)n * CD + c];
        cnt += 1.f;
    }
    if (cur >= 0) {
        atomicAdd(&g_gsum[(int)cur * CD + c], acc);
        if (c == 0) atomicAdd(&g_gcnt[(int)cur], cnt);
    }
}

// ---------------- final linear ----------------
__global__ void k_final(const float* __restrict__ W, const float* __restrict__ b,
                        float* __restrict__ out)
{
    int t = blockIdx.x * blockDim.x + threadIdx.x;
    if (t >= NG * CD) return;
    int g = t >> 7, z = t & 127;
    float inv = 1.f / fmaxf(g_gcnt[g], 1.f);
    float acc = 0.f;
#pragma unroll 8
    for (int c = 0; c < CD; c++)
        acc += g_gsum[g * CD + c] * W[c * CD + z];
    out[t] = acc * inv + b[z];
}

// ---------------- host orchestration ----------------
extern "C" void kernel_launch(void* const* d_in, const int* in_sizes, int n_in,
                              void* d_out, int out_size)
{
    const float* x     = (const float*)d_in[0];
    const void*  eidx  = d_in[1];
    const void*  batch = d_in[2];
    const float* lin_W = (const float*)d_in[21];
    const float* lin_b = (const float*)d_in[22];

    const int N = in_sizes[2];
    const int E = in_sizes[1] / 2;

    float *xl, *xr, *hbuf, *gsum, *gcnt;
    int *cnt, *rowptr, *bsum, *pos, *ssrc;
    unsigned short *ahi, *alo, *bhi, *blo;
    cudaGetSymbolAddress((void**)&xl,     g_xl);
    cudaGetSymbolAddress((void**)&xr,     g_xr);
    cudaGetSymbolAddress((void**)&hbuf,   g_h);
    cudaGetSymbolAddress((void**)&gsum,   g_gsum);
    cudaGetSymbolAddress((void**)&gcnt,   g_gcnt);
    cudaGetSymbolAddress((void**)&cnt,    g_cnt);
    cudaGetSymbolAddress((void**)&rowptr, g_rowptr);
    cudaGetSymbolAddress((void**)&bsum,   g_bsum);
    cudaGetSymbolAddress((void**)&pos,    g_pos);
    cudaGetSymbolAddress((void**)&ssrc,   g_ssrc);
    cudaGetSymbolAddress((void**)&ahi,    g_ahi);
    cudaGetSymbolAddress((void**)&alo,    g_alo);
    cudaGetSymbolAddress((void**)&bhi,    g_bhi);
    cudaGetSymbolAddress((void**)&blo,    g_blo);

    const int MMA_SMEM = 131072;
    cudaFuncSetAttribute(k_mma, cudaFuncAttributeMaxDynamicSharedMemorySize, MMA_SMEM);

    // ---- one-time: index dtype + CSR-by-dst build ----
    k_detect<<<1, 256>>>((const unsigned int*)eidx, 4096);
    k_zero_i<<<(N + 255) / 256, 256>>>(cnt, N);
    k_hist<<<(E + 255) / 256, 256>>>(eidx, cnt, E);
    k_scanA<<<NB_SCAN, 256>>>(cnt, rowptr, bsum, N);
    k_scanB<<<1, 256>>>(bsum, NB_SCAN);
    k_scanC<<<(N + 256) / 256, 256>>>(rowptr, bsum, pos, N, E);
    k_scatter<<<(E + 255) / 256, 256>>>(eidx, rowptr, pos, ssrc, E);

    for (int l = 0; l < 3; l++) {
        const float* Wl  = (const float*)d_in[3 + 6 * l + 0];
        const float* bl  = (const float*)d_in[3 + 6 * l + 1];
        const float* Wr  = (const float*)d_in[3 + 6 * l + 2];
        const float* br  = (const float*)d_in[3 + 6 * l + 3];
        const float* att = (const float*)d_in[3 + 6 * l + 4];
        const float* bb  = (const float*)d_in[3 + 6 * l + 5];

        if (l == 0) {
            k_gemm3<<<2048, 256>>>(x, Wl, bl, Wr, br, xl, xr, N);
        } else {
            k_prep_w<<<64, 256>>>(Wl, Wr, bhi, blo);
            dim3 gg(8, NT_M);
            k_mma<<<gg, 256, MMA_SMEM>>>(ahi, alo, bhi, blo, bl, br, xl, xr, N);
        }

        // fused scores + softmax + aggregation + epilogue (one warp per dst)
        k_edge<<<(N * 32 + 255) / 256, 256>>>(rowptr, ssrc, xl, xr, att, bb,
                                              hbuf, ahi, alo, N,
                                              (l == 2) ? 1 : 0, (l < 2) ? 1 : 0);
    }

    k_fill4<<<8, 256>>>((float4*)gsum, 0.f, NG * CD / 4);
    k_fill4<<<1, 16>>>((float4*)gcnt, 0.f, NG / 4);
    k_pool<<<(N + 63) / 64, 128>>>(hbuf, batch, N);
    k_final<<<(NG * CD + 255) / 256, 256>>>(lin_W, lin_b, (float*)d_out);
}

// round 14
// speedup vs baseline: 3.7075x; 1.0422x over previous
#include <cuda_runtime.h>
#include <cuda_bf16.h>
#include <cstdint>

#define NN   50000
#define EE   400000
#define NH   4
#define CD   128
#define HC   512
#define NG   64
#define NT_M 391          // ceil(50000/128) M-tiles
#define TILE_ELEMS 16384  // 128x128 bf16 tile
#define NB_SCAN 196       // ceil(50000/256)

// ---------------- device scratch ----------------
__device__ float g_xl[(size_t)NN * HC];
__device__ float g_xr[(size_t)NN * HC];
__device__ float g_h[(size_t)NN * CD];
__device__ float g_gsum[NG * CD];
__device__ float g_gcnt[NG];
__device__ int   g_is64;
// CSR-by-dst (built once per launch; dst is layer-invariant)
__device__ int g_cnt[NN];
__device__ int g_rowptr[NN + 1];
__device__ int g_bsum[256];
__device__ int g_pos[NN];
__device__ int g_ssrc[EE];
// row-major bf16 hi/lo operands for tensor-core GEMM (zero-init covers tail rows)
__device__ __align__(16) unsigned short g_ahi[(size_t)NT_M * TILE_ELEMS];
__device__ __align__(16) unsigned short g_alo[(size_t)NT_M * TILE_ELEMS];
__device__ __align__(16) unsigned short g_bhi[2 * 128 * 512];   // [side][k][n]
__device__ __align__(16) unsigned short g_blo[2 * 128 * 512];

// ---------------- generic helpers ----------------
__device__ __forceinline__ long long ld_idx(const void* p, long long i, int is64) {
    if (is64) return ((const long long*)p)[i];
    return (long long)((const int*)p)[i];
}

// ---------------- mma.sync building blocks ----------------
__device__ __forceinline__ uint32_t smem_u32(const void* p) {
    uint32_t a;
    asm("{ .reg .u64 t; cvta.to.shared.u64 t, %1; cvt.u32.u64 %0, t; }" : "=r"(a) : "l"(p));
    return a;
}
__device__ __forceinline__ void ldsm_x4(uint32_t* r, uint32_t addr) {
    asm volatile("ldmatrix.sync.aligned.m8n8.x4.shared.b16 {%0,%1,%2,%3}, [%4];"
                 : "=r"(r[0]), "=r"(r[1]), "=r"(r[2]), "=r"(r[3]) : "r"(addr));
}
__device__ __forceinline__ void ldsm_x4_t(uint32_t* r, uint32_t addr) {
    asm volatile("ldmatrix.sync.aligned.m8n8.x4.trans.shared.b16 {%0,%1,%2,%3}, [%4];"
                 : "=r"(r[0]), "=r"(r[1]), "=r"(r[2]), "=r"(r[3]) : "r"(addr));
}
__device__ __forceinline__ void mma_bf16(float* d, const uint32_t* a, const uint32_t* b) {
    asm volatile("mma.sync.aligned.m16n8k16.row.col.f32.bf16.bf16.f32 "
                 "{%0,%1,%2,%3}, {%4,%5,%6,%7}, {%8,%9}, {%0,%1,%2,%3};"
                 : "+f"(d[0]), "+f"(d[1]), "+f"(d[2]), "+f"(d[3])
                 : "r"(a[0]), "r"(a[1]), "r"(a[2]), "r"(a[3]), "r"(b[0]), "r"(b[1]));
}

// ---------------- index dtype detection ----------------
__global__ void k_detect(const unsigned int* __restrict__ w, int npairs) {
    __shared__ int s_any;
    if (threadIdx.x == 0) s_any = 0;
    __syncthreads();
    int any = 0;
    for (int i = threadIdx.x; i < npairs; i += blockDim.x)
        if (w[2 * i + 1] != 0u) any = 1;
    if (any) atomicOr(&s_any, 1);
    __syncthreads();
    if (threadIdx.x == 0) g_is64 = s_any ? 0 : 1;
}

// ---------------- fills ----------------
__global__ void k_fill4(float4* __restrict__ p, float v, int n4) {
    float4 q = make_float4(v, v, v, v);
    for (int i = blockIdx.x * blockDim.x + threadIdx.x; i < n4; i += gridDim.x * blockDim.x)
        p[i] = q;
}
__global__ void k_zero_i(int* __restrict__ p, int n) {
    int i = blockIdx.x * blockDim.x + threadIdx.x;
    if (i < n) p[i] = 0;
}

// ---------------- CSR build: histogram + scan + scatter ----------------
__global__ void k_hist(const void* __restrict__ eidx, int* __restrict__ cnt, int E) {
    int e = blockIdx.x * blockDim.x + threadIdx.x;
    if (e >= E) return;
    int d = (int)ld_idx(eidx, (long long)E + e, g_is64);
    atomicAdd(&cnt[d], 1);
}
__global__ void k_scanA(const int* __restrict__ cnt, int* __restrict__ rowptr,
                        int* __restrict__ bsum, int n) {
    __shared__ int sh[256];
    int i = blockIdx.x * 256 + threadIdx.x;
    int v = (i < n) ? cnt[i] : 0;
    sh[threadIdx.x] = v;
    __syncthreads();
#pragma unroll
    for (int o = 1; o < 256; o <<= 1) {
        int t = (threadIdx.x >= o) ? sh[threadIdx.x - o] : 0;
        __syncthreads();
        sh[threadIdx.x] += t;
        __syncthreads();
    }
    if (i < n) rowptr[i] = sh[threadIdx.x] - v;   // exclusive
    if (threadIdx.x == 255) bsum[blockIdx.x] = sh[255];
}
__global__ void k_scanB(int* __restrict__ bsum, int nb) {
    __shared__ int sh[256];
    int v = (threadIdx.x < nb) ? bsum[threadIdx.x] : 0;
    sh[threadIdx.x] = v;
    __syncthreads();
#pragma unroll
    for (int o = 1; o < 256; o <<= 1) {
        int t = (threadIdx.x >= o) ? sh[threadIdx.x - o] : 0;
        __syncthreads();
        sh[threadIdx.x] += t;
        __syncthreads();
    }
    if (threadIdx.x < nb) bsum[threadIdx.x] = sh[threadIdx.x] - v;  // exclusive
}
__global__ void k_scanC(int* __restrict__ rowptr, const int* __restrict__ bsum,
                        int* __restrict__ pos, int n, int E) {
    int i = blockIdx.x * 256 + threadIdx.x;
    if (i < n) { rowptr[i] += bsum[blockIdx.x]; pos[i] = 0; }
    if (i == n) rowptr[n] = E;
}
__global__ void k_scatter(const void* __restrict__ eidx, const int* __restrict__ rowptr,
                          int* __restrict__ pos, int* __restrict__ ssrc, int E) {
    int e = blockIdx.x * blockDim.x + threadIdx.x;
    if (e >= E) return;
    int is64 = g_is64;
    int s = (int)ld_idx(eidx, e, is64);
    int d = (int)ld_idx(eidx, (long long)E + e, is64);
    int p = rowptr[d] + atomicAdd(&pos[d], 1);
    ssrc[p] = s;
}

// ---------------- layer-0 GEMM (K=3): xl and xr in one pass ----------------
__global__ __launch_bounds__(256) void k_gemm3(
    const float* __restrict__ x,
    const float* __restrict__ Wl, const float* __restrict__ bl,
    const float* __restrict__ Wr, const float* __restrict__ br,
    float* __restrict__ xl, float* __restrict__ xr, int N)
{
    __shared__ float s[1536 * 2 + 512 * 2];
    float* sWl = s;          float* sWr = s + 1536;
    float* sbl = s + 3072;   float* sbr = s + 3584;
    for (int i = threadIdx.x; i < 1536; i += 256) { sWl[i] = Wl[i]; sWr[i] = Wr[i]; }
    for (int i = threadIdx.x; i < 512;  i += 256) { sbl[i] = bl[i]; sbr[i] = br[i]; }
    __syncthreads();
    int total = N * 128;
    for (int t = blockIdx.x * blockDim.x + threadIdx.x; t < total; t += gridDim.x * blockDim.x) {
        int n = t >> 7, jv = (t & 127) << 2;
        float x0 = x[n * 3 + 0], x1 = x[n * 3 + 1], x2 = x[n * 3 + 2];
        {
            float4 w0 = *(float4*)&sWl[jv], w1 = *(float4*)&sWl[512 + jv], w2 = *(float4*)&sWl[1024 + jv];
            float4 b = *(float4*)&sbl[jv];
            float4 o;
            o.x = x0 * w0.x + x1 * w1.x + x2 * w2.x + b.x;
            o.y = x0 * w0.y + x1 * w1.y + x2 * w2.y + b.y;
            o.z = x0 * w0.z + x1 * w1.z + x2 * w2.z + b.z;
            o.w = x0 * w0.w + x1 * w1.w + x2 * w2.w + b.w;
            *(float4*)(xl + (size_t)n * HC + jv) = o;
        }
        {
            float4 w0 = *(float4*)&sWr[jv], w1 = *(float4*)&sWr[512 + jv], w2 = *(float4*)&sWr[1024 + jv];
            float4 b = *(float4*)&sbr[jv];
            float4 o;
            o.x = x0 * w0.x + x1 * w1.x + x2 * w2.x + b.x;
            o.y = x0 * w0.y + x1 * w1.y + x2 * w2.y + b.y;
            o.z = x0 * w0.z + x1 * w1.z + x2 * w2.z + b.z;
            o.w = x0 * w0.w + x1 * w1.w + x2 * w2.w + b.w;
            *(float4*)(xr + (size_t)n * HC + jv) = o;
        }
    }
}

// ---------------- weight prep: W[128,512] -> hi/lo bf16 row-major ----------------
__global__ void k_prep_w(const float* __restrict__ Wl, const float* __restrict__ Wr,
                         unsigned short* __restrict__ bhi, unsigned short* __restrict__ blo)
{
    int t = blockIdx.x * blockDim.x + threadIdx.x;
    if (t >= 16384) return;
    int side = t >> 13;
    int idx8 = (t & 8191) << 3;
    const float* W = side ? Wr : Wl;
    __align__(16) __nv_bfloat16 hi[8], lo[8];
#pragma unroll
    for (int j = 0; j < 8; j++) {
        float v = W[idx8 + j];
        __nv_bfloat16 h = __float2bfloat16(v);
        hi[j] = h;
        lo[j] = __float2bfloat16(v - __bfloat162float(h));
    }
    *(uint4*)(bhi + side * 65536 + idx8) = *(uint4*)hi;
    *(uint4*)(blo + side * 65536 + idx8) = *(uint4*)lo;
}

// ---------------- tensor-core GEMM via mma.sync (verified R11/R12) ----------------
__global__ __launch_bounds__(256) void k_mma(
    const unsigned short* __restrict__ ahi, const unsigned short* __restrict__ alo,
    const unsigned short* __restrict__ bhi_g, const unsigned short* __restrict__ blo_g,
    const float* __restrict__ bl, const float* __restrict__ br,
    float* __restrict__ xl, float* __restrict__ xr, int M)
{
    extern __shared__ __align__(16) char smem[];
    const int mt = blockIdx.y, nt8 = blockIdx.x;
    const int side = nt8 >> 2, ntile = nt8 & 3;
    const int tid = threadIdx.x, wid = tid >> 5, lane = tid & 31;

    {
        const char* gA0 = (const char*)ahi + (size_t)mt * 32768;
        const char* gA1 = (const char*)alo + (size_t)mt * 32768;
        const char* gB0 = (const char*)bhi_g + (size_t)side * 131072;
        const char* gB1 = (const char*)blo_g + (size_t)side * 131072;
#pragma unroll 2
        for (int i = tid; i < 2048; i += 256) {
            int r = i >> 4, g = i & 15;
            int half = g >> 3, gg = g & 7;
            int dst = half * 16384 + r * 128 + ((gg * 16) ^ ((r & 7) << 4));
            *(uint4*)(smem + dst)          = *(const uint4*)(gA0 + r * 256 + g * 16);
            *(uint4*)(smem + 32768 + dst)  = *(const uint4*)(gA1 + r * 256 + g * 16);
            *(uint4*)(smem + 65536 + dst)  = *(const uint4*)(gB0 + r * 1024 + ntile * 256 + g * 16);
            *(uint4*)(smem + 98304 + dst)  = *(const uint4*)(gB1 + r * 1024 + ntile * 256 + g * 16);
        }
    }
    __syncthreads();

    const uint32_t sbase = smem_u32(smem);
    const int m0 = (wid >> 1) * 32, n0 = (wid & 1) * 64;

    float acc[2][8][4];
#pragma unroll
    for (int i = 0; i < 2; i++)
#pragma unroll
        for (int j = 0; j < 8; j++)
#pragma unroll
            for (int q = 0; q < 4; q++) acc[i][j][q] = 0.f;

#pragma unroll
    for (int ks = 0; ks < 8; ks++) {
        uint32_t aH[2][4], aL[2][4];
        {
            int cb = ((ks & 3) << 5) + ((lane >> 4) << 4);
#pragma unroll
            for (int mt2 = 0; mt2 < 2; mt2++) {
                int rr = m0 + mt2 * 16 + (lane & 15);
                uint32_t ad = sbase + (ks >> 2) * 16384 + rr * 128 + (cb ^ ((rr & 7) << 4));
                ldsm_x4(aH[mt2], ad);
                ldsm_x4(aL[mt2], ad + 32768);
            }
        }
        int rowk = ks * 16 + (lane & 15);
        int swk = (rowk & 7) << 4;
#pragma unroll
        for (int nc = 0; nc < 4; nc++) {
            int nb = n0 + nc * 16;
            uint32_t cbyte = ((nb & 63) << 1) + ((lane >> 4) << 4);
            uint32_t ad = sbase + 65536 + (nb >> 6) * 16384 + rowk * 128 + (cbyte ^ swk);
            uint32_t bH[4], bL[4];
            ldsm_x4_t(bH, ad);
            ldsm_x4_t(bL, ad + 32768);
#pragma unroll
            for (int mt2 = 0; mt2 < 2; mt2++) {
#pragma unroll
                for (int j = 0; j < 2; j++) {
                    float* d = acc[mt2][nc * 2 + j];
                    mma_bf16(d, aH[mt2], bH + 2 * j);
                    mma_bf16(d, aH[mt2], bL + 2 * j);
                    mma_bf16(d, aL[mt2], bH + 2 * j);
                }
            }
        }
    }

    const float* bias = side ? br : bl;
    float* out = side ? xr : xl;
    const int rbase = mt * 128 + m0;
#pragma unroll
    for (int mt2 = 0; mt2 < 2; mt2++) {
        int r0 = rbase + mt2 * 16 + (lane >> 2);
#pragma unroll
        for (int nt = 0; nt < 8; nt++) {
            int c = ntile * 128 + n0 + nt * 8 + (lane & 3) * 2;
            float2 b2 = *(const float2*)(bias + c);
            if (r0 < M) {
                float2 v = make_float2(acc[mt2][nt][0] + b2.x, acc[mt2][nt][1] + b2.y);
                *(float2*)(out + (size_t)r0 * 512 + c) = v;
            }
            if (r0 + 8 < M) {
                float2 v = make_float2(acc[mt2][nt][2] + b2.x, acc[mt2][nt][3] + b2.y);
                *(float2*)(out + (size_t)(r0 + 8) * 512 + c) = v;
            }
        }
    }
}

// ---------------- fused edge kernel: one warp per dst, online softmax ----------------
// v2: software-pipelined (1-edge lookahead gather) + branch-uniform softmax update
// (p is warp-uniform after the butterfly -> no divergence; common path does 1 exp,
//  no accumulator rescale). Streaming hints protect xl's L2 residency.
__global__ __launch_bounds__(256) void k_edge(
    const int* __restrict__ rowptr, const int* __restrict__ ssrc,
    const float* __restrict__ xl, const float* __restrict__ xr,
    const float* __restrict__ att, const float* __restrict__ bias,
    float* __restrict__ hout,
    unsigned short* __restrict__ ahi, unsigned short* __restrict__ alo,
    int N, int wh, int wab)
{
    int w = (blockIdx.x * blockDim.x + threadIdx.x) >> 5;
    int lane = threadIdx.x & 31;
    if (w >= N) return;
    int rs = rowptr[w], re = rowptr[w + 1];

    const float4* xrd = (const float4*)(xr + (size_t)w * HC);
    float4 r0 = __ldcs(xrd + lane), r1 = __ldcs(xrd + 32 + lane);
    float4 r2 = __ldcs(xrd + 64 + lane), r3 = __ldcs(xrd + 96 + lane);
    const float4* at4 = (const float4*)att;
    float4 w0 = at4[lane], w1 = at4[32 + lane], w2 = at4[64 + lane], w3 = at4[96 + lane];

    float m0 = -1e30f, m1 = -1e30f, m2 = -1e30f, m3 = -1e30f;
    float dn0 = 0.f, dn1 = 0.f, dn2 = 0.f, dn3 = 0.f;
    float4 ac0 = make_float4(0, 0, 0, 0), ac1 = ac0, ac2 = ac0, ac3 = ac0;

    // prologue: prefetch first edge's row
    float4 a0, a1, a2, a3;
    {
        int s = (rs < re) ? ssrc[rs] : 0;
        const float4* xls = (const float4*)(xl + (size_t)s * HC);
        a0 = xls[lane]; a1 = xls[32 + lane]; a2 = xls[64 + lane]; a3 = xls[96 + lane];
    }

    for (int j = rs; j < re; j++) {
        float4 c0 = a0, c1 = a1, c2 = a2, c3 = a3;
        // prefetch next edge's row (safe dummy index 0 on last iteration)
        {
            int sn = (j + 1 < re) ? ssrc[j + 1] : 0;
            const float4* xn = (const float4*)(xl + (size_t)sn * HC);
            a0 = xn[lane]; a1 = xn[32 + lane]; a2 = xn[64 + lane]; a3 = xn[96 + lane];
        }

#define LR(u) ((u) > 0.f ? (u) : 0.2f * (u))
#define DOTLR(a, r, wv) (LR(a.x + r.x) * wv.x + LR(a.y + r.y) * wv.y + \
                         LR(a.z + r.z) * wv.z + LR(a.w + r.w) * wv.w)
        float p0 = DOTLR(c0, r0, w0);
        float p1 = DOTLR(c1, r1, w1);
        float p2 = DOTLR(c2, r2, w2);
        float p3 = DOTLR(c3, r3, w3);
#undef DOTLR
#undef LR
#pragma unroll
        for (int o = 16; o > 0; o >>= 1) {
            p0 += __shfl_xor_sync(0xffffffffu, p0, o);
            p1 += __shfl_xor_sync(0xffffffffu, p1, o);
            p2 += __shfl_xor_sync(0xffffffffu, p2, o);
            p3 += __shfl_xor_sync(0xffffffffu, p3, o);
        }
        // branch-uniform online softmax update per head
        if (p0 > m0) {
            float sc = __expf(m0 - p0); m0 = p0;
            dn0 = dn0 * sc + 1.f;
            ac0.x = ac0.x * sc + c0.x; ac0.y = ac0.y * sc + c0.y;
            ac0.z = ac0.z * sc + c0.z; ac0.w = ac0.w * sc + c0.w;
        } else {
            float pe = __expf(p0 - m0);
            dn0 += pe;
            ac0.x += pe * c0.x; ac0.y += pe * c0.y;
            ac0.z += pe * c0.z; ac0.w += pe * c0.w;
        }
        if (p1 > m1) {
            float sc = __expf(m1 - p1); m1 = p1;
            dn1 = dn1 * sc + 1.f;
            ac1.x = ac1.x * sc + c1.x; ac1.y = ac1.y * sc + c1.y;
            ac1.z = ac1.z * sc + c1.z; ac1.w = ac1.w * sc + c1.w;
        } else {
            float pe = __expf(p1 - m1);
            dn1 += pe;
            ac1.x += pe * c1.x; ac1.y += pe * c1.y;
            ac1.z += pe * c1.z; ac1.w += pe * c1.w;
        }
        if (p2 > m2) {
            float sc = __expf(m2 - p2); m2 = p2;
            dn2 = dn2 * sc + 1.f;
            ac2.x = ac2.x * sc + c2.x; ac2.y = ac2.y * sc + c2.y;
            ac2.z = ac2.z * sc + c2.z; ac2.w = ac2.w * sc + c2.w;
        } else {
            float pe = __expf(p2 - m2);
            dn2 += pe;
            ac2.x += pe * c2.x; ac2.y += pe * c2.y;
            ac2.z += pe * c2.z; ac2.w += pe * c2.w;
        }
        if (p3 > m3) {
            float sc = __expf(m3 - p3); m3 = p3;
            dn3 = dn3 * sc + 1.f;
            ac3.x = ac3.x * sc + c3.x; ac3.y = ac3.y * sc + c3.y;
            ac3.z = ac3.z * sc + c3.z; ac3.w = ac3.w * sc + c3.w;
        } else {
            float pe = __expf(p3 - m3);
            dn3 += pe;
            ac3.x += pe * c3.x; ac3.y += pe * c3.y;
            ac3.z += pe * c3.z; ac3.w += pe * c3.w;
        }
    }

    float i0 = dn0 > 0.f ? 0.25f / dn0 : 0.f;
    float i1 = dn1 > 0.f ? 0.25f / dn1 : 0.f;
    float i2 = dn2 > 0.f ? 0.25f / dn2 : 0.f;
    float i3 = dn3 > 0.f ? 0.25f / dn3 : 0.f;

    int c0i = lane * 4;
    float4 b4 = *(const float4*)(bias + c0i);
    float v[4];
    v[0] = ac0.x * i0 + ac1.x * i1 + ac2.x * i2 + ac3.x * i3 + b4.x;
    v[1] = ac0.y * i0 + ac1.y * i1 + ac2.y * i2 + ac3.y * i3 + b4.y;
    v[2] = ac0.z * i0 + ac1.z * i1 + ac2.z * i2 + ac3.z * i3 + b4.z;
    v[3] = ac0.w * i0 + ac1.w * i1 + ac2.w * i2 + ac3.w * i3 + b4.w;

    __align__(8) __nv_bfloat16 hi[4], lo[4];
#pragma unroll
    for (int j = 0; j < 4; j++) {
        float e = v[j] > 0.f ? v[j] : (expf(v[j]) - 1.f);
        v[j] = e;
        __nv_bfloat16 h = __float2bfloat16(e);
        hi[j] = h;
        lo[j] = __float2bfloat16(e - __bfloat162float(h));
    }
    if (wh)
        __stcs((float4*)(hout + (size_t)w * CD + c0i), make_float4(v[0], v[1], v[2], v[3]));
    if (wab) {
        __stcs((uint2*)(ahi + (size_t)w * CD + c0i), *(uint2*)hi);
        __stcs((uint2*)(alo + (size_t)w * CD + c0i), *(uint2*)lo);
    }
}

// ---------------- global mean pool (batch sorted) ----------------
__global__ void k_pool(const float* __restrict__ h, const void* __restrict__ batch, int N)
{
    int c = threadIdx.x;
    int n0 = blockIdx.x * 64;
    int n1 = n0 + 64; if (n1 > N) n1 = N;
    int is64 = g_is64;
    long long cur = -1; float acc = 0.f, cnt = 0.f;
    for (int n = n0; n < n1; n++) {
        long long g = ld_idx(batch, n, is64);
        if (g != cur) {
            if (cur >= 0) {
                atomicAdd(&g_gsum[(int)cur * CD + c], acc);
                if (c == 0) atomicAdd(&g_gcnt[(int)cur], cnt);
            }
            cur = g; acc = 0.f; cnt = 0.f;
        }
        acc += h[(size_t)n * CD + c];
        cnt += 1.f;
    }
    if (cur >= 0) {
        atomicAdd(&g_gsum[(int)cur * CD + c], acc);
        if (c == 0) atomicAdd(&g_gcnt[(int)cur], cnt);
    }
}

// ---------------- final linear ----------------
__global__ void k_final(const float* __restrict__ W, const float* __restrict__ b,
                        float* __restrict__ out)
{
    int t = blockIdx.x * blockDim.x + threadIdx.x;
    if (t >= NG * CD) return;
    int g = t >> 7, z = t & 127;
    float inv = 1.f / fmaxf(g_gcnt[g], 1.f);
    float acc = 0.f;
#pragma unroll 8
    for (int c = 0; c < CD; c++)
        acc += g_gsum[g * CD + c] * W[c * CD + z];
    out[t] = acc * inv + b[z];
}

// ---------------- host orchestration ----------------
extern "C" void kernel_launch(void* const* d_in, const int* in_sizes, int n_in,
                              void* d_out, int out_size)
{
    const float* x     = (const float*)d_in[0];
    const void*  eidx  = d_in[1];
    const void*  batch = d_in[2];
    const float* lin_W = (const float*)d_in[21];
    const float* lin_b = (const float*)d_in[22];

    const int N = in_sizes[2];
    const int E = in_sizes[1] / 2;

    float *xl, *xr, *hbuf, *gsum, *gcnt;
    int *cnt, *rowptr, *bsum, *pos, *ssrc;
    unsigned short *ahi, *alo, *bhi, *blo;
    cudaGetSymbolAddress((void**)&xl,     g_xl);
    cudaGetSymbolAddress((void**)&xr,     g_xr);
    cudaGetSymbolAddress((void**)&hbuf,   g_h);
    cudaGetSymbolAddress((void**)&gsum,   g_gsum);
    cudaGetSymbolAddress((void**)&gcnt,   g_gcnt);
    cudaGetSymbolAddress((void**)&cnt,    g_cnt);
    cudaGetSymbolAddress((void**)&rowptr, g_rowptr);
    cudaGetSymbolAddress((void**)&bsum,   g_bsum);
    cudaGetSymbolAddress((void**)&pos,    g_pos);
    cudaGetSymbolAddress((void**)&ssrc,   g_ssrc);
    cudaGetSymbolAddress((void**)&ahi,    g_ahi);
    cudaGetSymbolAddress((void**)&alo,    g_alo);
    cudaGetSymbolAddress((void**)&bhi,    g_bhi);
    cudaGetSymbolAddress((void**)&blo,    g_blo);

    const int MMA_SMEM = 131072;
    cudaFuncSetAttribute(k_mma, cudaFuncAttributeMaxDynamicSharedMemorySize, MMA_SMEM);

    // ---- one-time: index dtype + CSR-by-dst build ----
    k_detect<<<1, 256>>>((const unsigned int*)eidx, 4096);
    k_zero_i<<<(N + 255) / 256, 256>>>(cnt, N);
    k_hist<<<(E + 255) / 256, 256>>>(eidx, cnt, E);
    k_scanA<<<NB_SCAN, 256>>>(cnt, rowptr, bsum, N);
    k_scanB<<<1, 256>>>(bsum, NB_SCAN);
    k_scanC<<<(N + 256) / 256, 256>>>(rowptr, bsum, pos, N, E);
    k_scatter<<<(E + 255) / 256, 256>>>(eidx, rowptr, pos, ssrc, E);

    for (int l = 0; l < 3; l++) {
        const float* Wl  = (const float*)d_in[3 + 6 * l + 0];
        const float* bl  = (const float*)d_in[3 + 6 * l + 1];
        const float* Wr  = (const float*)d_in[3 + 6 * l + 2];
        const float* br  = (const float*)d_in[3 + 6 * l + 3];
        const float* att = (const float*)d_in[3 + 6 * l + 4];
        const float* bb  = (const float*)d_in[3 + 6 * l + 5];

        if (l == 0) {
            k_gemm3<<<2048, 256>>>(x, Wl, bl, Wr, br, xl, xr, N);
        } else {
            k_prep_w<<<64, 256>>>(Wl, Wr, bhi, blo);
            dim3 gg(8, NT_M);
            k_mma<<<gg, 256, MMA_SMEM>>>(ahi, alo, bhi, blo, bl, br, xl, xr, N);
        }

        // fused scores + softmax + aggregation + epilogue (one warp per dst)
        k_edge<<<(N * 32 + 255) / 256, 256>>>(rowptr, ssrc, xl, xr, att, bb,
                                              hbuf, ahi, alo, N,
                                              (l == 2) ? 1 : 0, (l < 2) ? 1 : 0);
    }

    k_fill4<<<8, 256>>>((float4*)gsum, 0.f, NG * CD / 4);
    k_fill4<<<1, 16>>>((float4*)gcnt, 0.f, NG / 4);
    k_pool<<<(N + 63) / 64, 128>>>(hbuf, batch, N);
    k_final<<<(NG * CD + 255) / 256, 256>>>(lin_W, lin_b, (float*)d_out);
}

// round 16
// speedup vs baseline: 3.8103x; 1.0277x over previous
#include <cuda_runtime.h>
#include <cuda_bf16.h>
#include <cuda_fp16.h>
#include <cstdint>

#define NN   50000
#define EE   400000
#define NH   4
#define CD   128
#define HC   512
#define NG   64
#define NT_M 391          // ceil(50000/128) M-tiles
#define TILE_ELEMS 16384  // 128x128 bf16 tile
#define NB_SCAN 196       // ceil(50000/256)

// ---------------- device scratch ----------------
__device__ __half g_xl[(size_t)NN * HC];   // fp16: 51.2 MB -> xl gather table fits L2
__device__ __half g_xr[(size_t)NN * HC];
__device__ float g_h[(size_t)NN * CD];
__device__ float g_gsum[NG * CD];
__device__ float g_gcnt[NG];
__device__ int   g_is64;
// CSR-by-dst (built once per launch; dst is layer-invariant)
__device__ int g_cnt[NN];
__device__ int g_rowptr[NN + 1];
__device__ int g_bsum[256];
__device__ int g_pos[NN];
__device__ int g_ssrc[EE];
// row-major bf16 hi/lo operands for tensor-core GEMM (zero-init covers tail rows)
__device__ __align__(16) unsigned short g_ahi[(size_t)NT_M * TILE_ELEMS];
__device__ __align__(16) unsigned short g_alo[(size_t)NT_M * TILE_ELEMS];
__device__ __align__(16) unsigned short g_bhi[2 * 128 * 512];   // [side][k][n]
__device__ __align__(16) unsigned short g_blo[2 * 128 * 512];

// ---------------- generic helpers ----------------
__device__ __forceinline__ long long ld_idx(const void* p, long long i, int is64) {
    if (is64) return ((const long long*)p)[i];
    return (long long)((const int*)p)[i];
}
__device__ __forceinline__ float4 h4_to_f4(uint2 u) {
    float2 f0 = __half22float2(*reinterpret_cast<__half2*>(&u.x));
    float2 f1 = __half22float2(*reinterpret_cast<__half2*>(&u.y));
    return make_float4(f0.x, f0.y, f1.x, f1.y);
}
__device__ __forceinline__ uint2 f4_to_h4(float4 v) {
    __half2 h0 = __floats2half2_rn(v.x, v.y);
    __half2 h1 = __floats2half2_rn(v.z, v.w);
    uint2 u;
    u.x = *reinterpret_cast<uint32_t*>(&h0);
    u.y = *reinterpret_cast<uint32_t*>(&h1);
    return u;
}

// ---------------- mma.sync building blocks ----------------
__device__ __forceinline__ uint32_t smem_u32(const void* p) {
    uint32_t a;
    asm("{ .reg .u64 t; cvta.to.shared.u64 t, %1; cvt.u32.u64 %0, t; }" : "=r"(a) : "l"(p));
    return a;
}
__device__ __forceinline__ void ldsm_x4(uint32_t* r, uint32_t addr) {
    asm volatile("ldmatrix.sync.aligned.m8n8.x4.shared.b16 {%0,%1,%2,%3}, [%4];"
                 : "=r"(r[0]), "=r"(r[1]), "=r"(r[2]), "=r"(r[3]) : "r"(addr));
}
__device__ __forceinline__ void ldsm_x4_t(uint32_t* r, uint32_t addr) {
    asm volatile("ldmatrix.sync.aligned.m8n8.x4.trans.shared.b16 {%0,%1,%2,%3}, [%4];"
                 : "=r"(r[0]), "=r"(r[1]), "=r"(r[2]), "=r"(r[3]) : "r"(addr));
}
__device__ __forceinline__ void mma_bf16(float* d, const uint32_t* a, const uint32_t* b) {
    asm volatile("mma.sync.aligned.m16n8k16.row.col.f32.bf16.bf16.f32 "
                 "{%0,%1,%2,%3}, {%4,%5,%6,%7}, {%8,%9}, {%0,%1,%2,%3};"
                 : "+f"(d[0]), "+f"(d[1]), "+f"(d[2]), "+f"(d[3])
                 : "r"(a[0]), "r"(a[1]), "r"(a[2]), "r"(a[3]), "r"(b[0]), "r"(b[1]));
}

// ---------------- index dtype detection ----------------
__global__ void k_detect(const unsigned int* __restrict__ w, int npairs) {
    __shared__ int s_any;
    if (threadIdx.x == 0) s_any = 0;
    __syncthreads();
    int any = 0;
    for (int i = threadIdx.x; i < npairs; i += blockDim.x)
        if (w[2 * i + 1] != 0u) any = 1;
    if (any) atomicOr(&s_any, 1);
    __syncthreads();
    if (threadIdx.x == 0) g_is64 = s_any ? 0 : 1;
}

// ---------------- fills ----------------
__global__ void k_fill4(float4* __restrict__ p, float v, int n4) {
    float4 q = make_float4(v, v, v, v);
    for (int i = blockIdx.x * blockDim.x + threadIdx.x; i < n4; i += gridDim.x * blockDim.x)
        p[i] = q;
}
__global__ void k_zero_i(int* __restrict__ p, int n) {
    int i = blockIdx.x * blockDim.x + threadIdx.x;
    if (i < n) p[i] = 0;
}

// ---------------- CSR build: histogram + scan + scatter ----------------
__global__ void k_hist(const void* __restrict__ eidx, int* __restrict__ cnt, int E) {
    int e = blockIdx.x * blockDim.x + threadIdx.x;
    if (e >= E) return;
    int d = (int)ld_idx(eidx, (long long)E + e, g_is64);
    atomicAdd(&cnt[d], 1);
}
__global__ void k_scanA(const int* __restrict__ cnt, int* __restrict__ rowptr,
                        int* __restrict__ bsum, int n) {
    __shared__ int sh[256];
    int i = blockIdx.x * 256 + threadIdx.x;
    int v = (i < n) ? cnt[i] : 0;
    sh[threadIdx.x] = v;
    __syncthreads();
#pragma unroll
    for (int o = 1; o < 256; o <<= 1) {
        int t = (threadIdx.x >= o) ? sh[threadIdx.x - o] : 0;
        __syncthreads();
        sh[threadIdx.x] += t;
        __syncthreads();
    }
    if (i < n) rowptr[i] = sh[threadIdx.x] - v;   // exclusive
    if (threadIdx.x == 255) bsum[blockIdx.x] = sh[255];
}
__global__ void k_scanB(int* __restrict__ bsum, int nb) {
    __shared__ int sh[256];
    int v = (threadIdx.x < nb) ? bsum[threadIdx.x] : 0;
    sh[threadIdx.x] = v;
    __syncthreads();
#pragma unroll
    for (int o = 1; o < 256; o <<= 1) {
        int t = (threadIdx.x >= o) ? sh[threadIdx.x - o] : 0;
        __syncthreads();
        sh[threadIdx.x] += t;
        __syncthreads();
    }
    if (threadIdx.x < nb) bsum[threadIdx.x] = sh[threadIdx.x] - v;  // exclusive
}
__global__ void k_scanC(int* __restrict__ rowptr, const int* __restrict__ bsum,
                        int* __restrict__ pos, int n, int E) {
    int i = blockIdx.x * 256 + threadIdx.x;
    if (i < n) { rowptr[i] += bsum[blockIdx.x]; pos[i] = 0; }
    if (i == n) rowptr[n] = E;
}
__global__ void k_scatter(const void* __restrict__ eidx, const int* __restrict__ rowptr,
                          int* __restrict__ pos, int* __restrict__ ssrc, int E) {
    int e = blockIdx.x * blockDim.x + threadIdx.x;
    if (e >= E) return;
    int is64 = g_is64;
    int s = (int)ld_idx(eidx, e, is64);
    int d = (int)ld_idx(eidx, (long long)E + e, is64);
    int p = rowptr[d] + atomicAdd(&pos[d], 1);
    ssrc[p] = s;
}

// ---------------- layer-0 GEMM (K=3): xl and xr in one pass (fp16 out) ----------------
__global__ __launch_bounds__(256) void k_gemm3(
    const float* __restrict__ x,
    const float* __restrict__ Wl, const float* __restrict__ bl,
    const float* __restrict__ Wr, const float* __restrict__ br,
    __half* __restrict__ xl, __half* __restrict__ xr, int N)
{
    __shared__ float s[1536 * 2 + 512 * 2];
    float* sWl = s;          float* sWr = s + 1536;
    float* sbl = s + 3072;   float* sbr = s + 3584;
    for (int i = threadIdx.x; i < 1536; i += 256) { sWl[i] = Wl[i]; sWr[i] = Wr[i]; }
    for (int i = threadIdx.x; i < 512;  i += 256) { sbl[i] = bl[i]; sbr[i] = br[i]; }
    __syncthreads();
    int total = N * 128;
    for (int t = blockIdx.x * blockDim.x + threadIdx.x; t < total; t += gridDim.x * blockDim.x) {
        int n = t >> 7, jv = (t & 127) << 2;
        float x0 = x[n * 3 + 0], x1 = x[n * 3 + 1], x2 = x[n * 3 + 2];
        {
            float4 w0 = *(float4*)&sWl[jv], w1 = *(float4*)&sWl[512 + jv], w2 = *(float4*)&sWl[1024 + jv];
            float4 b = *(float4*)&sbl[jv];
            float4 o;
            o.x = x0 * w0.x + x1 * w1.x + x2 * w2.x + b.x;
            o.y = x0 * w0.y + x1 * w1.y + x2 * w2.y + b.y;
            o.z = x0 * w0.z + x1 * w1.z + x2 * w2.z + b.z;
            o.w = x0 * w0.w + x1 * w1.w + x2 * w2.w + b.w;
            *(uint2*)(xl + (size_t)n * HC + jv) = f4_to_h4(o);
        }
        {
            float4 w0 = *(float4*)&sWr[jv], w1 = *(float4*)&sWr[512 + jv], w2 = *(float4*)&sWr[1024 + jv];
            float4 b = *(float4*)&sbr[jv];
            float4 o;
            o.x = x0 * w0.x + x1 * w1.x + x2 * w2.x + b.x;
            o.y = x0 * w0.y + x1 * w1.y + x2 * w2.y + b.y;
            o.z = x0 * w0.z + x1 * w1.z + x2 * w2.z + b.z;
            o.w = x0 * w0.w + x1 * w1.w + x2 * w2.w + b.w;
            *(uint2*)(xr + (size_t)n * HC + jv) = f4_to_h4(o);
        }
    }
}

// ---------------- weight prep: W[128,512] -> hi/lo bf16 row-major ----------------
__global__ void k_prep_w(const float* __restrict__ Wl, const float* __restrict__ Wr,
                         unsigned short* __restrict__ bhi, unsigned short* __restrict__ blo)
{
    int t = blockIdx.x * blockDim.x + threadIdx.x;
    if (t >= 16384) return;
    int side = t >> 13;
    int idx8 = (t & 8191) << 3;
    const float* W = side ? Wr : Wl;
    __align__(16) __nv_bfloat16 hi[8], lo[8];
#pragma unroll
    for (int j = 0; j < 8; j++) {
        float v = W[idx8 + j];
        __nv_bfloat16 h = __float2bfloat16(v);
        hi[j] = h;
        lo[j] = __float2bfloat16(v - __bfloat162float(h));
    }
    *(uint4*)(bhi + side * 65536 + idx8) = *(uint4*)hi;
    *(uint4*)(blo + side * 65536 + idx8) = *(uint4*)lo;
}

// ---------------- tensor-core GEMM via mma.sync (fp16 activation out) ----------------
__global__ __launch_bounds__(256) void k_mma(
    const unsigned short* __restrict__ ahi, const unsigned short* __restrict__ alo,
    const unsigned short* __restrict__ bhi_g, const unsigned short* __restrict__ blo_g,
    const float* __restrict__ bl, const float* __restrict__ br,
    __half* __restrict__ xl, __half* __restrict__ xr, int M)
{
    extern __shared__ __align__(16) char smem[];
    const int mt = blockIdx.y, nt8 = blockIdx.x;
    const int side = nt8 >> 2, ntile = nt8 & 3;
    const int tid = threadIdx.x, wid = tid >> 5, lane = tid & 31;

    {
        const char* gA0 = (const char*)ahi + (size_t)mt * 32768;
        const char* gA1 = (const char*)alo + (size_t)mt * 32768;
        const char* gB0 = (const char*)bhi_g + (size_t)side * 131072;
        const char* gB1 = (const char*)blo_g + (size_t)side * 131072;
#pragma unroll 2
        for (int i = tid; i < 2048; i += 256) {
            int r = i >> 4, g = i & 15;
            int half_ = g >> 3, gg = g & 7;
            int dst = half_ * 16384 + r * 128 + ((gg * 16) ^ ((r & 7) << 4));
            *(uint4*)(smem + dst)          = *(const uint4*)(gA0 + r * 256 + g * 16);
            *(uint4*)(smem + 32768 + dst)  = *(const uint4*)(gA1 + r * 256 + g * 16);
            *(uint4*)(smem + 65536 + dst)  = *(const uint4*)(gB0 + r * 1024 + ntile * 256 + g * 16);
            *(uint4*)(smem + 98304 + dst)  = *(const uint4*)(gB1 + r * 1024 + ntile * 256 + g * 16);
        }
    }
    __syncthreads();

    const uint32_t sbase = smem_u32(smem);
    const int m0 = (wid >> 1) * 32, n0 = (wid & 1) * 64;

    float acc[2][8][4];
#pragma unroll
    for (int i = 0; i < 2; i++)
#pragma unroll
        for (int j = 0; j < 8; j++)
#pragma unroll
            for (int q = 0; q < 4; q++) acc[i][j][q] = 0.f;

#pragma unroll
    for (int ks = 0; ks < 8; ks++) {
        uint32_t aH[2][4], aL[2][4];
        {
            int cb = ((ks & 3) << 5) + ((lane >> 4) << 4);
#pragma unroll
            for (int mt2 = 0; mt2 < 2; mt2++) {
                int rr = m0 + mt2 * 16 + (lane & 15);
                uint32_t ad = sbase + (ks >> 2) * 16384 + rr * 128 + (cb ^ ((rr & 7) << 4));
                ldsm_x4(aH[mt2], ad);
                ldsm_x4(aL[mt2], ad + 32768);
            }
        }
        int rowk = ks * 16 + (lane & 15);
        int swk = (rowk & 7) << 4;
#pragma unroll
        for (int nc = 0; nc < 4; nc++) {
            int nb = n0 + nc * 16;
            uint32_t cbyte = ((nb & 63) << 1) + ((lane >> 4) << 4);
            uint32_t ad = sbase + 65536 + (nb >> 6) * 16384 + rowk * 128 + (cbyte ^ swk);
            uint32_t bH[4], bL[4];
            ldsm_x4_t(bH, ad);
            ldsm_x4_t(bL, ad + 32768);
#pragma unroll
            for (int mt2 = 0; mt2 < 2; mt2++) {
#pragma unroll
                for (int j = 0; j < 2; j++) {
                    float* d = acc[mt2][nc * 2 + j];
                    mma_bf16(d, aH[mt2], bH + 2 * j);
                    mma_bf16(d, aH[mt2], bL + 2 * j);
                    mma_bf16(d, aL[mt2], bH + 2 * j);
                }
            }
        }
    }

    const float* bias = side ? br : bl;
    __half* out = side ? xr : xl;
    const int rbase = mt * 128 + m0;
#pragma unroll
    for (int mt2 = 0; mt2 < 2; mt2++) {
        int r0 = rbase + mt2 * 16 + (lane >> 2);
#pragma unroll
        for (int nt = 0; nt < 8; nt++) {
            int c = ntile * 128 + n0 + nt * 8 + (lane & 3) * 2;
            float2 b2 = *(const float2*)(bias + c);
            if (r0 < M) {
                __half2 h = __floats2half2_rn(acc[mt2][nt][0] + b2.x, acc[mt2][nt][1] + b2.y);
                *(__half2*)(out + (size_t)r0 * 512 + c) = h;
            }
            if (r0 + 8 < M) {
                __half2 h = __floats2half2_rn(acc[mt2][nt][2] + b2.x, acc[mt2][nt][3] + b2.y);
                *(__half2*)(out + (size_t)(r0 + 8) * 512 + c) = h;
            }
        }
    }
}

// ---------------- fused edge kernel: one warp per dst, online softmax ----------------
// fp16 xl/xr: the gathered xl table (51.2 MB) fits L2 -> gathers are L2 hits.
// Pipelined 1-edge lookahead; branch-uniform softmax update; streaming stores.
__global__ __launch_bounds__(256) void k_edge(
    const int* __restrict__ rowptr, const int* __restrict__ ssrc,
    const __half* __restrict__ xl, const __half* __restrict__ xr,
    const float* __restrict__ att, const float* __restrict__ bias,
    float* __restrict__ hout,
    unsigned short* __restrict__ ahi, unsigned short* __restrict__ alo,
    int N, int wh, int wab)
{
    int w = (blockIdx.x * blockDim.x + threadIdx.x) >> 5;
    int lane = threadIdx.x & 31;
    if (w >= N) return;
    int rs = rowptr[w], re = rowptr[w + 1];

    const uint2* xrd = (const uint2*)(xr + (size_t)w * HC);
    float4 r0 = h4_to_f4(__ldcs(xrd + lane)),      r1 = h4_to_f4(__ldcs(xrd + 32 + lane));
    float4 r2 = h4_to_f4(__ldcs(xrd + 64 + lane)), r3 = h4_to_f4(__ldcs(xrd + 96 + lane));
    const float4* at4 = (const float4*)att;
    float4 w0 = at4[lane], w1 = at4[32 + lane], w2 = at4[64 + lane], w3 = at4[96 + lane];

    float m0 = -1e30f, m1 = -1e30f, m2 = -1e30f, m3 = -1e30f;
    float dn0 = 0.f, dn1 = 0.f, dn2 = 0.f, dn3 = 0.f;
    float4 ac0 = make_float4(0, 0, 0, 0), ac1 = ac0, ac2 = ac0, ac3 = ac0;

    // prologue: prefetch first edge's row (raw halves; convert at use)
    uint2 q0, q1, q2, q3;
    {
        int s = (rs < re) ? ssrc[rs] : 0;
        const uint2* xls = (const uint2*)(xl + (size_t)s * HC);
        q0 = xls[lane]; q1 = xls[32 + lane]; q2 = xls[64 + lane]; q3 = xls[96 + lane];
    }

    for (int j = rs; j < re; j++) {
        float4 c0 = h4_to_f4(q0), c1 = h4_to_f4(q1), c2 = h4_to_f4(q2), c3 = h4_to_f4(q3);
        // prefetch next edge's row (safe dummy index 0 on last iteration)
        {
            int sn = (j + 1 < re) ? ssrc[j + 1] : 0;
            const uint2* xn = (const uint2*)(xl + (size_t)sn * HC);
            q0 = xn[lane]; q1 = xn[32 + lane]; q2 = xn[64 + lane]; q3 = xn[96 + lane];
        }

#define LR(u) ((u) > 0.f ? (u) : 0.2f * (u))
#define DOTLR(a, r, wv) (LR(a.x + r.x) * wv.x + LR(a.y + r.y) * wv.y + \
                         LR(a.z + r.z) * wv.z + LR(a.w + r.w) * wv.w)
        float p0 = DOTLR(c0, r0, w0);
        float p1 = DOTLR(c1, r1, w1);
        float p2 = DOTLR(c2, r2, w2);
        float p3 = DOTLR(c3, r3, w3);
#undef DOTLR
#undef LR
#pragma unroll
        for (int o = 16; o > 0; o >>= 1) {
            p0 += __shfl_xor_sync(0xffffffffu, p0, o);
            p1 += __shfl_xor_sync(0xffffffffu, p1, o);
            p2 += __shfl_xor_sync(0xffffffffu, p2, o);
            p3 += __shfl_xor_sync(0xffffffffu, p3, o);
        }
        // branch-uniform online softmax update per head
        if (p0 > m0) {
            float sc = __expf(m0 - p0); m0 = p0;
            dn0 = dn0 * sc + 1.f;
            ac0.x = ac0.x * sc + c0.x; ac0.y = ac0.y * sc + c0.y;
            ac0.z = ac0.z * sc + c0.z; ac0.w = ac0.w * sc + c0.w;
        } else {
            float pe = __expf(p0 - m0);
            dn0 += pe;
            ac0.x += pe * c0.x; ac0.y += pe * c0.y;
            ac0.z += pe * c0.z; ac0.w += pe * c0.w;
        }
        if (p1 > m1) {
            float sc = __expf(m1 - p1); m1 = p1;
            dn1 = dn1 * sc + 1.f;
            ac1.x = ac1.x * sc + c1.x; ac1.y = ac1.y * sc + c1.y;
            ac1.z = ac1.z * sc + c1.z; ac1.w = ac1.w * sc + c1.w;
        } else {
            float pe = __expf(p1 - m1);
            dn1 += pe;
            ac1.x += pe * c1.x; ac1.y += pe * c1.y;
            ac1.z += pe * c1.z; ac1.w += pe * c1.w;
        }
        if (p2 > m2) {
            float sc = __expf(m2 - p2); m2 = p2;
            dn2 = dn2 * sc + 1.f;
            ac2.x = ac2.x * sc + c2.x; ac2.y = ac2.y * sc + c2.y;
            ac2.z = ac2.z * sc + c2.z; ac2.w = ac2.w * sc + c2.w;
        } else {
            float pe = __expf(p2 - m2);
            dn2 += pe;
            ac2.x += pe * c2.x; ac2.y += pe * c2.y;
            ac2.z += pe * c2.z; ac2.w += pe * c2.w;
        }
        if (p3 > m3) {
            float sc = __expf(m3 - p3); m3 = p3;
            dn3 = dn3 * sc + 1.f;
            ac3.x = ac3.x * sc + c3.x; ac3.y = ac3.y * sc + c3.y;
            ac3.z = ac3.z * sc + c3.z; ac3.w = ac3.w * sc + c3.w;
        } else {
            float pe = __expf(p3 - m3);
            dn3 += pe;
            ac3.x += pe * c3.x; ac3.y += pe * c3.y;
            ac3.z += pe * c3.z; ac3.w += pe * c3.w;
        }
    }

    float i0 = dn0 > 0.f ? 0.25f / dn0 : 0.f;
    float i1 = dn1 > 0.f ? 0.25f / dn1 : 0.f;
    float i2 = dn2 > 0.f ? 0.25f / dn2 : 0.f;
    float i3 = dn3 > 0.f ? 0.25f / dn3 : 0.f;

    int c0i = lane * 4;
    float4 b4 = *(const float4*)(bias + c0i);
    float v[4];
    v[0] = ac0.x * i0 + ac1.x * i1 + ac2.x * i2 + ac3.x * i3 + b4.x;
    v[1] = ac0.y * i0 + ac1.y * i1 + ac2.y * i2 + ac3.y * i3 + b4.y;
    v[2] = ac0.z * i0 + ac1.z * i1 + ac2.z * i2 + ac3.z * i3 + b4.z;
    v[3] = ac0.w * i0 + ac1.w * i1 + ac2.w * i2 + ac3.w * i3 + b4.w;

    __align__(8) __nv_bfloat16 hi[4], lo[4];
#pragma unroll
    for (int j = 0; j < 4; j++) {
        float e = v[j] > 0.f ? v[j] : (expf(v[j]) - 1.f);
        v[j] = e;
        __nv_bfloat16 h = __float2bfloat16(e);
        hi[j] = h;
        lo[j] = __float2bfloat16(e - __bfloat162float(h));
    }
    if (wh)
        __stcs((float4*)(hout + (size_t)w * CD + c0i), make_float4(v[0], v[1], v[2], v[3]));
    if (wab) {
        __stcs((uint2*)(ahi + (size_t)w * CD + c0i), *(uint2*)hi);
        __stcs((uint2*)(alo + (size_t)w * CD + c0i), *(uint2*)lo);
    }
}

// ---------------- global mean pool (batch sorted) ----------------
__global__ void k_pool(const float* __restrict__ h, const void* __restrict__ batch, int N)
{
    int c = threadIdx.x;
    int n0 = blockIdx.x * 64;
    int n1 = n0 + 64; if (n1 > N) n1 = N;
    int is64 = g_is64;
    long long cur = -1; float acc = 0.f, cnt = 0.f;
    for (int n = n0; n < n1; n++) {
        long long g = ld_idx(batch, n, is64);
        if (g != cur) {
            if (cur >= 0) {
                atomicAdd(&g_gsum[(int)cur * CD + c], acc);
                if (c == 0) atomicAdd(&g_gcnt[(int)cur], cnt);
            }
            cur = g; acc = 0.f; cnt = 0.f;
        }
        acc += h[(size_t)n * CD + c];
        cnt += 1.f;
    }
    if (cur >= 0) {
        atomicAdd(&g_gsum[(int)cur * CD + c], acc);
        if (c == 0) atomicAdd(&g_gcnt[(int)cur], cnt);
    }
}

// ---------------- final linear ----------------
__global__ void k_final(const float* __restrict__ W, const float* __restrict__ b,
                        float* __restrict__ out)
{
    int t = blockIdx.x * blockDim.x + threadIdx.x;
    if (t >= NG * CD) return;
    int g = t >> 7, z = t & 127;
    float inv = 1.f / fmaxf(g_gcnt[g], 1.f);
    float acc = 0.f;
#pragma unroll 8
    for (int c = 0; c < CD; c++)
        acc += g_gsum[g * CD + c] * W[c * CD + z];
    out[t] = acc * inv + b[z];
}

// ---------------- host orchestration ----------------
extern "C" void kernel_launch(void* const* d_in, const int* in_sizes, int n_in,
                              void* d_out, int out_size)
{
    const float* x     = (const float*)d_in[0];
    const void*  eidx  = d_in[1];
    const void*  batch = d_in[2];
    const float* lin_W = (const float*)d_in[21];
    const float* lin_b = (const float*)d_in[22];

    const int N = in_sizes[2];
    const int E = in_sizes[1] / 2;

    float *hbuf, *gsum, *gcnt;
    __half *xl, *xr;
    int *cnt, *rowptr, *bsum, *pos, *ssrc;
    unsigned short *ahi, *alo, *bhi, *blo;
    cudaGetSymbolAddress((void**)&xl,     g_xl);
    cudaGetSymbolAddress((void**)&xr,     g_xr);
    cudaGetSymbolAddress((void**)&hbuf,   g_h);
    cudaGetSymbolAddress((void**)&gsum,   g_gsum);
    cudaGetSymbolAddress((void**)&gcnt,   g_gcnt);
    cudaGetSymbolAddress((void**)&cnt,    g_cnt);
    cudaGetSymbolAddress((void**)&rowptr, g_rowptr);
    cudaGetSymbolAddress((void**)&bsum,   g_bsum);
    cudaGetSymbolAddress((void**)&pos,    g_pos);
    cudaGetSymbolAddress((void**)&ssrc,   g_ssrc);
    cudaGetSymbolAddress((void**)&ahi,    g_ahi);
    cudaGetSymbolAddress((void**)&alo,    g_alo);
    cudaGetSymbolAddress((void**)&bhi,    g_bhi);
    cudaGetSymbolAddress((void**)&blo,    g_blo);

    const int MMA_SMEM = 131072;
    cudaFuncSetAttribute(k_mma, cudaFuncAttributeMaxDynamicSharedMemorySize, MMA_SMEM);

    // ---- one-time: index dtype + CSR-by-dst build ----
    k_detect<<<1, 256>>>((const unsigned int*)eidx, 4096);
    k_zero_i<<<(N + 255) / 256, 256>>>(cnt, N);
    k_hist<<<(E + 255) / 256, 256>>>(eidx, cnt, E);
    k_scanA<<<NB_SCAN, 256>>>(cnt, rowptr, bsum, N);
    k_scanB<<<1, 256>>>(bsum, NB_SCAN);
    k_scanC<<<(N + 256) / 256, 256>>>(rowptr, bsum, pos, N, E);
    k_scatter<<<(E + 255) / 256, 256>>>(eidx, rowptr, pos, ssrc, E);

    for (int l = 0; l < 3; l++) {
        const float* Wl  = (const float*)d_in[3 + 6 * l + 0];
        const float* bl  = (const float*)d_in[3 + 6 * l + 1];
        const float* Wr  = (const float*)d_in[3 + 6 * l + 2];
        const float* br  = (const float*)d_in[3 + 6 * l + 3];
        const float* att = (const float*)d_in[3 + 6 * l + 4];
        const float* bb  = (const float*)d_in[3 + 6 * l + 5];

        if (l == 0) {
            k_gemm3<<<2048, 256>>>(x, Wl, bl, Wr, br, xl, xr, N);
        } else {
            k_prep_w<<<64, 256>>>(Wl, Wr, bhi, blo);
            dim3 gg(8, NT_M);
            k_mma<<<gg, 256, MMA_SMEM>>>(ahi, alo, bhi, blo, bl, br, xl, xr, N);
        }

        // fused scores + softmax + aggregation + epilogue (one warp per dst)
        k_edge<<<(N * 32 + 255) / 256, 256>>>(rowptr, ssrc, xl, xr, att, bb,
                                              hbuf, ahi, alo, N,
                                              (l == 2) ? 1 : 0, (l < 2) ? 1 : 0);
    }

    k_fill4<<<8, 256>>>((float4*)gsum, 0.f, NG * CD / 4);
    k_fill4<<<1, 16>>>((float4*)gcnt, 0.f, NG / 4);
    k_pool<<<(N + 63) / 64, 128>>>(hbuf, batch, N);
    k_final<<<(NG * CD + 255) / 256, 256>>>(lin_W, lin_b, (float*)d_out);
}